// round 14
// baseline (speedup 1.0000x reference)
#include <cuda_runtime.h>
#include <cuda_bf16.h>
#include <math.h>

// ---------------- problem constants ----------------
#define Bb    64
#define Ss    1024
#define Dd    256
#define Hh    256
#define H2    512
#define Ff    128
#define Tt    64
#define Ll    8
#define NSEG  128
#define DIN   1152
#define G4    2048           // 4 * H2
#define NROWS 65536          // B * S
#define NSEGT 8192           // B * NSEG
#define Vv    50000

// ---------------- scratch (static device, no allocs) ----------------
__device__ __nv_bfloat16 g_decinb[NSEGT * DIN];          // bf16 dec_in
__device__ __nv_bfloat16 g_U[(size_t)NROWS * 768];       // bf16 conv taps
__device__ __nv_bfloat16 g_Wallb[768 * Dd];              // bf16 stacked conv W
__device__ __nv_bfloat16 g_embb[(size_t)Vv * Dd];        // bf16 embed table
__device__ __nv_bfloat16 g_Wihb[(size_t)G4 * DIN];       // bf16 W_ih
__device__ __nv_bfloat16 g_Wfcb[Tt * H2];                // bf16 W_fc
__device__ float g_gx[(size_t)NSEGT * G4];
__device__ __nv_bfloat16 g_hb[(size_t)129 * Bb * H2];    // bf16 h
__device__ unsigned g_bar2[2];

// ---------------- helpers ----------------
__device__ __forceinline__ float sigmf(float x) { return 1.f / (1.f + __expf(-x)); }
__device__ __forceinline__ float tanhfast(float x) { return 2.f / (1.f + __expf(-2.f * x)) - 1.f; }
__device__ __forceinline__ unsigned packbf(float lo, float hi) {
    unsigned d;
    asm("cvt.rn.bf16x2.f32 %0, %1, %2;" : "=r"(d) : "f"(hi), "f"(lo));
    return d;
}
__device__ __forceinline__ float bflo(unsigned u) { return __uint_as_float(u << 16); }
__device__ __forceinline__ float bfhi(unsigned u) { return __uint_as_float(u & 0xffff0000u); }

#define MMA_BF16(acc, a0, a1, a2, a3, b0, b1)                                  \
    asm("mma.sync.aligned.m16n8k16.row.col.f32.bf16.bf16.f32 "                 \
        "{%0,%1,%2,%3},{%4,%5,%6,%7},{%8,%9},{%0,%1,%2,%3};"                   \
        : "+f"(acc[0]), "+f"(acc[1]), "+f"(acc[2]), "+f"(acc[3])               \
        : "r"(a0), "r"(a1), "r"(a2), "r"(a3), "r"(b0), "r"(b1))

#define LDSM_X4(r0, r1, r2, r3, addr)                                          \
    asm volatile("ldmatrix.sync.aligned.m8n8.x4.shared.b16 {%0,%1,%2,%3}, [%4];" \
                 : "=r"(r0), "=r"(r1), "=r"(r2), "=r"(r3) : "r"(addr))

#define CP_ASYNC16(dst, src)                                                   \
    asm volatile("cp.async.cg.shared.global [%0], [%1], 16;\n" ::              \
                 "r"(dst), "l"(src))

// ================= 128x128 bf16 GEMM (gates): C fp32 = A @ B^T =============
#define BBM 128
#define BBN 128
#define BBK 64
#define GEMMB_SMEM (2 * (BBM + BBN) * 144)   // 73728 B

__global__ __launch_bounds__(256, 2) void gemmb(
    const __nv_bfloat16* __restrict__ A, const __nv_bfloat16* __restrict__ Bw,
    float* __restrict__ C, int M, int N, int K)
{
    extern __shared__ unsigned short bsm[];

    int tid = threadIdx.x;
    int mBase = blockIdx.y * BBM, nBase = blockIdx.x * BBN;

    int w = tid >> 5, lane = tid & 31;
    int grp = lane >> 2, tig = lane & 3;
    int wm = w & 1, wn = w >> 1;       // 2x4 warp grid, warp tile 64x32

    unsigned smbase = (unsigned)__cvta_generic_to_shared(bsm);
    unsigned bbase = smbase + 2 * BBM * 144;

    unsigned aAddr0 = smbase + (unsigned)((wm * 64 + (lane & 15)) * 144 + ((lane >> 4) << 4));
    unsigned bAddr0 = bbase + (unsigned)((wn * 32 + (lane & 15)) * 144 + ((lane >> 4) << 4));

    float acc[4][4][4];
#pragma unroll
    for (int mt = 0; mt < 4; mt++)
#pragma unroll
        for (int nt = 0; nt < 4; nt++)
#pragma unroll
            for (int i = 0; i < 4; i++) acc[mt][nt][i] = 0.f;

    int nkt = K / BBK;

#define BLOAD(s, kt) do {                                                       \
        int koff = (kt) * BBK;                                                  \
        _Pragma("unroll")                                                       \
        for (int i = 0; i < 4; i++) {                                           \
            int cid = tid + i * 256;                                            \
            int row = cid >> 3, ch = cid & 7;                                   \
            const __nv_bfloat16* src = A + (size_t)(mBase + row) * K + koff + ch * 8; \
            unsigned dst = smbase + (unsigned)(((s) * BBM + row) * 144 + ch * 16);    \
            CP_ASYNC16(dst, src);                                               \
        }                                                                       \
        _Pragma("unroll")                                                       \
        for (int i = 0; i < 4; i++) {                                           \
            int cid = tid + i * 256;                                            \
            int row = cid >> 3, ch = cid & 7;                                   \
            const __nv_bfloat16* src = Bw + (size_t)(nBase + row) * K + koff + ch * 8; \
            unsigned dst = bbase + (unsigned)(((s) * BBN + row) * 144 + ch * 16);     \
            CP_ASYNC16(dst, src);                                               \
        }                                                                       \
        asm volatile("cp.async.commit_group;\n");                               \
    } while (0)

    BLOAD(0, 0);

    for (int kt = 0; kt < nkt; kt++) {
        int s = kt & 1;
        if (kt + 1 < nkt) {
            BLOAD((kt + 1) & 1, kt + 1);
            asm volatile("cp.async.wait_group 1;\n" ::: "memory");
        } else {
            asm volatile("cp.async.wait_group 0;\n" ::: "memory");
        }
        __syncthreads();

        unsigned aS = aAddr0 + (unsigned)(s * BBM * 144);
        unsigned bS = bAddr0 + (unsigned)(s * BBN * 144);
#pragma unroll
        for (int kc = 0; kc < 4; kc++) {
            unsigned kb = kc * 32;
            unsigned bfr[2][4];
#pragma unroll
            for (int ntp = 0; ntp < 2; ntp++)
                LDSM_X4(bfr[ntp][0], bfr[ntp][1], bfr[ntp][2], bfr[ntp][3],
                        bS + ntp * (16 * 144) + kb);
#pragma unroll
            for (int mt = 0; mt < 4; mt++) {
                unsigned a0, a1, a2, a3;
                LDSM_X4(a0, a1, a2, a3, aS + mt * (16 * 144) + kb);
                MMA_BF16(acc[mt][0], a0, a1, a2, a3, bfr[0][0], bfr[0][2]);
                MMA_BF16(acc[mt][1], a0, a1, a2, a3, bfr[0][1], bfr[0][3]);
                MMA_BF16(acc[mt][2], a0, a1, a2, a3, bfr[1][0], bfr[1][2]);
                MMA_BF16(acc[mt][3], a0, a1, a2, a3, bfr[1][1], bfr[1][3]);
            }
        }
        __syncthreads();
    }

#pragma unroll
    for (int mt = 0; mt < 4; mt++) {
        int row0 = mBase + wm * 64 + mt * 16 + grp;
#pragma unroll
        for (int nt = 0; nt < 4; nt++) {
            int col = nBase + wn * 32 + nt * 8 + tig * 2;
            *(float2*)&C[(size_t)row0 * N + col] = make_float2(acc[mt][nt][0], acc[mt][nt][1]);
            *(float2*)&C[(size_t)(row0 + 8) * N + col] = make_float2(acc[mt][nt][2], acc[mt][nt][3]);
        }
    }
}

// ================= gathered bf16 GEMM, bf16 out (conv taps) =================
__global__ __launch_bounds__(256, 2) void gemmbg(
    const __nv_bfloat16* __restrict__ A, const __nv_bfloat16* __restrict__ Bw,
    __nv_bfloat16* __restrict__ C, int M, int N, int K,
    const int* __restrict__ gather)
{
    extern __shared__ unsigned short bsm[];
    __shared__ int rows_s[BBM];

    int tid = threadIdx.x;
    int mBase = blockIdx.y * BBM, nBase = blockIdx.x * BBN;
    if (tid < BBM) rows_s[tid] = gather[mBase + tid];
    __syncthreads();

    int w = tid >> 5, lane = tid & 31;
    int grp = lane >> 2, tig = lane & 3;
    int wm = w & 1, wn = w >> 1;

    unsigned smbase = (unsigned)__cvta_generic_to_shared(bsm);
    unsigned bbase = smbase + 2 * BBM * 144;

    unsigned aAddr0 = smbase + (unsigned)((wm * 64 + (lane & 15)) * 144 + ((lane >> 4) << 4));
    unsigned bAddr0 = bbase + (unsigned)((wn * 32 + (lane & 15)) * 144 + ((lane >> 4) << 4));

    float acc[4][4][4];
#pragma unroll
    for (int mt = 0; mt < 4; mt++)
#pragma unroll
        for (int nt = 0; nt < 4; nt++)
#pragma unroll
            for (int i = 0; i < 4; i++) acc[mt][nt][i] = 0.f;

    int nkt = K / BBK;

#define BGLOAD(s, kt) do {                                                      \
        int koff = (kt) * BBK;                                                  \
        _Pragma("unroll")                                                       \
        for (int i = 0; i < 4; i++) {                                           \
            int cid = tid + i * 256;                                            \
            int row = cid >> 3, ch = cid & 7;                                   \
            const __nv_bfloat16* src = A + (size_t)rows_s[row] * K + koff + ch * 8;   \
            unsigned dst = smbase + (unsigned)(((s) * BBM + row) * 144 + ch * 16);    \
            CP_ASYNC16(dst, src);                                               \
        }                                                                       \
        _Pragma("unroll")                                                       \
        for (int i = 0; i < 4; i++) {                                           \
            int cid = tid + i * 256;                                            \
            int row = cid >> 3, ch = cid & 7;                                   \
            const __nv_bfloat16* src = Bw + (size_t)(nBase + row) * K + koff + ch * 8; \
            unsigned dst = bbase + (unsigned)(((s) * BBN + row) * 144 + ch * 16);     \
            CP_ASYNC16(dst, src);                                               \
        }                                                                       \
        asm volatile("cp.async.commit_group;\n");                               \
    } while (0)

    BGLOAD(0, 0);

    for (int kt = 0; kt < nkt; kt++) {
        int s = kt & 1;
        if (kt + 1 < nkt) {
            BGLOAD((kt + 1) & 1, kt + 1);
            asm volatile("cp.async.wait_group 1;\n" ::: "memory");
        } else {
            asm volatile("cp.async.wait_group 0;\n" ::: "memory");
        }
        __syncthreads();

        unsigned aS = aAddr0 + (unsigned)(s * BBM * 144);
        unsigned bS = bAddr0 + (unsigned)(s * BBN * 144);
#pragma unroll
        for (int kc = 0; kc < 4; kc++) {
            unsigned kb = kc * 32;
            unsigned bfr[2][4];
#pragma unroll
            for (int ntp = 0; ntp < 2; ntp++)
                LDSM_X4(bfr[ntp][0], bfr[ntp][1], bfr[ntp][2], bfr[ntp][3],
                        bS + ntp * (16 * 144) + kb);
#pragma unroll
            for (int mt = 0; mt < 4; mt++) {
                unsigned a0, a1, a2, a3;
                LDSM_X4(a0, a1, a2, a3, aS + mt * (16 * 144) + kb);
                MMA_BF16(acc[mt][0], a0, a1, a2, a3, bfr[0][0], bfr[0][2]);
                MMA_BF16(acc[mt][1], a0, a1, a2, a3, bfr[0][1], bfr[0][3]);
                MMA_BF16(acc[mt][2], a0, a1, a2, a3, bfr[1][0], bfr[1][2]);
                MMA_BF16(acc[mt][3], a0, a1, a2, a3, bfr[1][1], bfr[1][3]);
            }
        }
        __syncthreads();
    }

#pragma unroll
    for (int mt = 0; mt < 4; mt++) {
        int row0 = mBase + wm * 64 + mt * 16 + grp;
#pragma unroll
        for (int nt = 0; nt < 4; nt++) {
            int col = nBase + wn * 32 + nt * 8 + tig * 2;
            *(unsigned*)&C[(size_t)row0 * N + col] = packbf(acc[mt][nt][0], acc[mt][nt][1]);
            *(unsigned*)&C[(size_t)(row0 + 8) * N + col] = packbf(acc[mt][nt][2], acc[mt][nt][3]);
        }
    }
}

// ======== fused logits GEMM (bf16) + log_softmax + output permutation ========
#define LBM 128
#define LBN 64
#define LSM_SMEM (2 * (LBM + LBN) * 144)   // 55296 B

__global__ __launch_bounds__(256, 2) void gemm_lsm(
    const __nv_bfloat16* __restrict__ A, const __nv_bfloat16* __restrict__ Bw,
    float* __restrict__ out)
{
    extern __shared__ unsigned short bsm[];
    float* ls = (float*)bsm;

    int tid = threadIdx.x;
    int mBase = blockIdx.x * LBM;

    int w = tid >> 5, lane = tid & 31;
    int grp = lane >> 2, tig = lane & 3;
    int wm = w & 3, wn = w >> 2;

    unsigned smbase = (unsigned)__cvta_generic_to_shared(bsm);
    unsigned bbase = smbase + 2 * LBM * 144;

    unsigned aAddr0 = smbase + (unsigned)((wm * 32 + (lane & 15)) * 144 + ((lane >> 4) << 4));
    unsigned bAddr0 = bbase + (unsigned)((wn * 32 + (lane & 15)) * 144 + ((lane >> 4) << 4));

    float acc[2][4][4];
#pragma unroll
    for (int mt = 0; mt < 2; mt++)
#pragma unroll
        for (int nt = 0; nt < 4; nt++)
#pragma unroll
            for (int i = 0; i < 4; i++) acc[mt][nt][i] = 0.f;

#define LLOAD(s, kt) do {                                                       \
        int koff = (kt) * BBK;                                                  \
        _Pragma("unroll")                                                       \
        for (int i = 0; i < 4; i++) {                                           \
            int cid = tid + i * 256;                                            \
            int row = cid >> 3, ch = cid & 7;                                   \
            const __nv_bfloat16* src = A + (size_t)(mBase + row) * H2 + koff + ch * 8; \
            unsigned dst = smbase + (unsigned)(((s) * LBM + row) * 144 + ch * 16);     \
            CP_ASYNC16(dst, src);                                               \
        }                                                                       \
        _Pragma("unroll")                                                       \
        for (int i = 0; i < 2; i++) {                                           \
            int cid = tid + i * 256;                                            \
            int row = cid >> 3, ch = cid & 7;                                   \
            const __nv_bfloat16* src = Bw + (size_t)row * H2 + koff + ch * 8;   \
            unsigned dst = bbase + (unsigned)(((s) * LBN + row) * 144 + ch * 16);     \
            CP_ASYNC16(dst, src);                                               \
        }                                                                       \
        asm volatile("cp.async.commit_group;\n");                               \
    } while (0)

    LLOAD(0, 0);

    const int nkt = H2 / BBK;   // 8
    for (int kt = 0; kt < nkt; kt++) {
        int s = kt & 1;
        if (kt + 1 < nkt) {
            LLOAD((kt + 1) & 1, kt + 1);
            asm volatile("cp.async.wait_group 1;\n" ::: "memory");
        } else {
            asm volatile("cp.async.wait_group 0;\n" ::: "memory");
        }
        __syncthreads();

        unsigned aS = aAddr0 + (unsigned)(s * LBM * 144);
        unsigned bS = bAddr0 + (unsigned)(s * LBN * 144);
#pragma unroll
        for (int kc = 0; kc < 4; kc++) {
            unsigned kb = kc * 32;
            unsigned bfr[2][4];
#pragma unroll
            for (int ntp = 0; ntp < 2; ntp++)
                LDSM_X4(bfr[ntp][0], bfr[ntp][1], bfr[ntp][2], bfr[ntp][3],
                        bS + ntp * (16 * 144) + kb);
#pragma unroll
            for (int mt = 0; mt < 2; mt++) {
                unsigned a0, a1, a2, a3;
                LDSM_X4(a0, a1, a2, a3, aS + mt * (16 * 144) + kb);
                MMA_BF16(acc[mt][0], a0, a1, a2, a3, bfr[0][0], bfr[0][2]);
                MMA_BF16(acc[mt][1], a0, a1, a2, a3, bfr[0][1], bfr[0][3]);
                MMA_BF16(acc[mt][2], a0, a1, a2, a3, bfr[1][0], bfr[1][2]);
                MMA_BF16(acc[mt][3], a0, a1, a2, a3, bfr[1][1], bfr[1][3]);
            }
        }
        __syncthreads();
    }

#pragma unroll
    for (int mt = 0; mt < 2; mt++) {
        int row0 = wm * 32 + mt * 16 + grp;
#pragma unroll
        for (int nt = 0; nt < 4; nt++) {
            int col = wn * 32 + nt * 8 + tig * 2;
            *(float2*)&ls[row0 * 68 + col] = make_float2(acc[mt][nt][0], acc[mt][nt][1]);
            *(float2*)&ls[(row0 + 8) * 68 + col] = make_float2(acc[mt][nt][2], acc[mt][nt][3]);
        }
    }
    __syncthreads();

#pragma unroll 4
    for (int rr = 0; rr < 16; rr++) {
        int row = w * 16 + rr;
        float2 v = *(const float2*)&ls[row * 68 + lane * 2];
        float m = fmaxf(v.x, v.y);
#pragma unroll
        for (int o = 16; o; o >>= 1) m = fmaxf(m, __shfl_xor_sync(0xffffffffu, m, o));
        float s = expf(v.x - m) + expf(v.y - m);
#pragma unroll
        for (int o = 16; o; o >>= 1) s += __shfl_xor_sync(0xffffffffu, s, o);
        float lse = m + logf(s);
        int r = mBase + row;
        int t = r >> 6, bb = r & 63;
        *(float2*)&out[(size_t)(bb * NSEG + t) * Tt + lane * 2] =
            make_float2(v.x - lse, v.y - lse);
    }
}

// ------- fused prep: seg_feat | cvt_emb | cvt_wih | pack_wall | cvt_wfc | h0 -
#define PREP_S NSEGT
#define PREP_E 12500
#define PREP_W 2304
#define PREP_P 384
#define PREP_F 32
#define PREP_H 64
#define PREP_BLOCKS (PREP_S + PREP_E + PREP_W + PREP_P + PREP_F + PREP_H)

__global__ __launch_bounds__(256) void prep(
    const int* __restrict__ word_ids,
    const float* __restrict__ embed, const float* __restrict__ Wih,
    const float* __restrict__ w1, const float* __restrict__ w2,
    const float* __restrict__ w3, const float* __restrict__ Wfc,
    const float* __restrict__ enc)
{
    int bid = blockIdx.x, tid = threadIdx.x;
    if (bid < PREP_S) {
        int r = bid;
        int b = r >> 7, seg = r & 127;
        __shared__ int ids[8];
        if (tid < 8) ids[tid] = word_ids[b * Ss + seg * Ll + tid];
        __syncthreads();
        {
            float s = 0.f;
#pragma unroll
            for (int t = 0; t < 8; t++) s += embed[(size_t)ids[t] * Dd + tid];
            g_decinb[(size_t)r * DIN + tid] = __float2bfloat16(s * 0.125f);
        }
        for (int k = tid; k < H2; k += 256) {
            float s = 0.f;
#pragma unroll
            for (int t = 0; t < 8; t++) s += enc[(size_t)(b * Ss + seg * Ll + t) * H2 + k];
            g_decinb[(size_t)r * DIN + Dd + k] = __float2bfloat16(s * 0.125f);
        }
        return;
    }
    bid -= PREP_S;
    if (bid < PREP_E) {
        size_t i = ((size_t)bid * 256 + tid) * 4;
        float4 v = *(const float4*)(embed + i);
        *(uint2*)((unsigned short*)g_embb + i) =
            make_uint2(packbf(v.x, v.y), packbf(v.z, v.w));
        return;
    }
    bid -= PREP_E;
    if (bid < PREP_W) {
        size_t i = ((size_t)bid * 256 + tid) * 4;
        float4 v = *(const float4*)(Wih + i);
        *(uint2*)((unsigned short*)g_Wihb + i) =
            make_uint2(packbf(v.x, v.y), packbf(v.z, v.w));
        return;
    }
    bid -= PREP_W;
    if (bid < PREP_P) {
        int n = bid * 2 + (tid >> 7);
        int k = tid & 127;
        const float* src;
        if (n < 128)       src = w1 + n * Dd;
        else if (n < 384) { int m = n - 128; src = w2 + ((m & 127) * 2 + (m >> 7)) * Dd; }
        else              { int m = n - 384; src = w3 + ((m & 127) * 3 + (m >> 7)) * Dd; }
        *(unsigned*)&g_Wallb[n * Dd + k * 2] = packbf(src[k * 2], src[k * 2 + 1]);
        return;
    }
    bid -= PREP_P;
    if (bid < PREP_F) {
        size_t i = ((size_t)bid * 256 + tid) * 4;
        float4 v = *(const float4*)(Wfc + i);
        *(uint2*)((unsigned short*)g_Wfcb + i) =
            make_uint2(packbf(v.x, v.y), packbf(v.z, v.w));
        return;
    }
    bid -= PREP_F;
    {
        if (bid == 0 && tid < 2) g_bar2[tid] = 0;
        int b = bid;
        for (int j = tid; j < H2; j += 256) {
            float v = (j < Hh) ? enc[(size_t)(b * Ss + Ss - 1) * H2 + j]
                               : enc[(size_t)(b * Ss) * H2 + j];
            g_hb[(size_t)b * H2 + j] = __float2bfloat16(v);
        }
    }
}

// ---------------- conv tap-sum + relu + maxpool (vectorized bf16x2) ----------
__global__ __launch_bounds__(192) void conv_reduce(
    const float* __restrict__ b1, const float* __restrict__ b2, const float* __restrict__ b3)
{
    int r = blockIdx.x, tid = threadIdx.x;
    const unsigned* U = (const unsigned*)(g_U + (size_t)r * 8 * 768);
    unsigned* d = (unsigned*)(g_decinb + (size_t)r * DIN + 768);

    int which = tid >> 6, p = tid & 63;
    float mx = -1e30f, my = -1e30f;

    if (which == 0) {
#pragma unroll
        for (int t = 0; t < 8; t++) {
            unsigned u = U[t * 384 + p];
            mx = fmaxf(mx, bflo(u)); my = fmaxf(my, bfhi(u));
        }
        mx += b1[p * 2]; my += b1[p * 2 + 1];
    } else if (which == 1) {
#pragma unroll
        for (int t = 0; t < 7; t++) {
            unsigned u0 = U[t * 384 + 64 + p];
            unsigned u1 = U[(t + 1) * 384 + 128 + p];
            mx = fmaxf(mx, bflo(u0) + bflo(u1));
            my = fmaxf(my, bfhi(u0) + bfhi(u1));
        }
        mx += b2[p * 2]; my += b2[p * 2 + 1];
    } else {
#pragma unroll
        for (int t = 0; t < 6; t++) {
            unsigned u0 = U[t * 384 + 192 + p];
            unsigned u1 = U[(t + 1) * 384 + 256 + p];
            unsigned u2 = U[(t + 2) * 384 + 320 + p];
            mx = fmaxf(mx, bflo(u0) + bflo(u1) + bflo(u2));
            my = fmaxf(my, bfhi(u0) + bfhi(u1) + bfhi(u2));
        }
        mx += b3[p * 2]; my += b3[p * 2 + 1];
    }
    d[which * 64 + p] = packbf(fmaxf(mx, 0.f), fmaxf(my, 0.f));
}

// ========== bf16 scan: direct-L2 A-fragments (no smem staging) ==========
// 128 CTAs = 64 col-groups (8 units) x 2 batch-groups (32 rows); 16 warps.
// Warp (mt = w&1 row-half, kq = w>>1 K-slice of 64). A-fragments loaded
// straight from g_hb via ld.global.cg (write-once slots; coherent via the
// release/acquire barrier). Smem holds only pbuf.
#define SCAN_SMEM (8 * 32 * 34 * 4)   // 34816 B

__global__ __launch_bounds__(512, 1) void scan6d(const float* __restrict__ Whh)
{
    extern __shared__ float pbuf[];   // [8 kq][32 rows][34]

    int tid = threadIdx.x;
    int lane = tid & 31, w = tid >> 5;
    int grp = lane >> 2, tig = lane & 3;
    int mt = w & 1, kq = w >> 1;
    int cid = blockIdx.x;
    int bg = cid & 1;
    int j0 = (cid >> 1) * 8;

    unsigned bw[4][4][2];
#pragma unroll
    for (int nt = 0; nt < 4; nt++) {
        const float* wr = Whh + (size_t)(nt * H2 + j0 + grp) * H2 + kq * 64;
#pragma unroll
        for (int kc = 0; kc < 4; kc++) {
            const float* p = wr + kc * 16 + tig * 2;
            bw[nt][kc][0] = packbf(p[0], p[1]);
            bw[nt][kc][1] = packbf(p[8], p[9]);
        }
    }

    unsigned* pcount = &g_bar2[bg];

    float c_st = 0.f;
    int b_hat = tid >> 3, jj = tid & 7;     // epilogue item (tid<256)
    int row_global = bg * 32 + b_hat;
    size_t gx_base = (size_t)(row_global * NSEG) * G4 + (size_t)(j0 + jj);

    // per-lane A-fragment base (bf16 elements within one t-slot)
    size_t fbase = (size_t)(bg * 32 + mt * 16 + grp) * H2 + kq * 64 + tig * 2;

    float gxi = 0.f, gxf = 0.f, gxg = 0.f, gxq = 0.f;
    if (tid < 256) {
        gxi = __ldg(&g_gx[gx_base]);
        gxf = __ldg(&g_gx[gx_base + 512]);
        gxg = __ldg(&g_gx[gx_base + 1024]);
        gxq = __ldg(&g_gx[gx_base + 1536]);
    }

    for (int t = 0; t < NSEG; t++) {
        // A-fragments straight from L2 (16 independent 32-bit loads)
        const __nv_bfloat16* hp = g_hb + (size_t)t * Bb * H2 + fbase;
        unsigned af[4][4];
#pragma unroll
        for (int kc = 0; kc < 4; kc++) {
            af[kc][0] = __ldcg((const unsigned*)(hp + kc * 16));
            af[kc][1] = __ldcg((const unsigned*)(hp + kc * 16 + 8 * H2));
            af[kc][2] = __ldcg((const unsigned*)(hp + kc * 16 + 8));
            af[kc][3] = __ldcg((const unsigned*)(hp + kc * 16 + 8 * H2 + 8));
        }

        float acc[4][4];
#pragma unroll
        for (int nt = 0; nt < 4; nt++)
#pragma unroll
            for (int i = 0; i < 4; i++) acc[nt][i] = 0.f;
#pragma unroll
        for (int kc = 0; kc < 4; kc++) {
#pragma unroll
            for (int nt = 0; nt < 4; nt++)
                MMA_BF16(acc[nt], af[kc][0], af[kc][1], af[kc][2], af[kc][3],
                         bw[nt][kc][0], bw[nt][kc][1]);
        }
        {
            float* pb = pbuf + kq * (32 * 34);
            int row = mt * 16 + grp;
#pragma unroll
            for (int nt = 0; nt < 4; nt++) {
                int c0 = nt * 8 + tig * 2;
                pb[row * 34 + c0]           = acc[nt][0];
                pb[row * 34 + c0 + 1]       = acc[nt][1];
                pb[(row + 8) * 34 + c0]     = acc[nt][2];
                pb[(row + 8) * 34 + c0 + 1] = acc[nt][3];
            }
        }
        __syncthreads();

        if (tid < 256) {
            float gsum[4];
#pragma unroll
            for (int q = 0; q < 4; q++) {
                int col = q * 8 + jj;
                float s = 0.f;
#pragma unroll
                for (int k = 0; k < 8; k++) s += pbuf[k * (32 * 34) + b_hat * 34 + col];
                gsum[q] = s;
            }
            float gi = gsum[0] + gxi;
            float gf = gsum[1] + gxf;
            float gg = gsum[2] + gxg;
            float go = gsum[3] + gxq;
            c_st = sigmf(gf) * c_st + sigmf(gi) * tanhfast(gg);
            float h = sigmf(go) * tanhfast(c_st);
            size_t ho = (size_t)(t + 1) * Bb * H2 + (size_t)row_global * H2 + j0 + jj;
            g_hb[ho] = __float2bfloat16(h);

            if (t + 1 < NSEG) {
                size_t gxo = gx_base + (size_t)(t + 1) * G4;
                gxi = __ldg(&g_gx[gxo]);
                gxf = __ldg(&g_gx[gxo + 512]);
                gxg = __ldg(&g_gx[gxo + 1024]);
                gxq = __ldg(&g_gx[gxo + 1536]);
            }
        }

        __syncthreads();
        if (t + 1 < NSEG) {
            if (tid == 0) {
                unsigned one = 1;
                asm volatile("red.release.gpu.global.add.u32 [%0], %1;"
                             :: "l"(pcount), "r"(one) : "memory");
                unsigned target = 64u * (unsigned)(t + 1);
                unsigned cur;
                do {
                    asm volatile("ld.acquire.gpu.global.u32 %0, [%1];"
                                 : "=r"(cur) : "l"(pcount));
                } while (cur < target);
            }
            __syncthreads();
        }
    }
}

// ---------------- launcher ----------------
extern "C" void kernel_launch(void* const* d_in, const int* in_sizes, int n_in,
                              void* d_out, int out_size)
{
    const int*   word_ids = (const int*)d_in[0];
    const float* embed    = (const float*)d_in[1];
    const float* enc      = (const float*)d_in[2];
    const float* w1       = (const float*)d_in[3];
    const float* b1       = (const float*)d_in[4];
    const float* w2       = (const float*)d_in[5];
    const float* b2       = (const float*)d_in[6];
    const float* w3       = (const float*)d_in[7];
    const float* b3       = (const float*)d_in[8];
    const float* Wih      = (const float*)d_in[9];
    const float* Whh      = (const float*)d_in[10];
    const float* Wfc      = (const float*)d_in[11];
    float* out = (float*)d_out;

    void *pU, *pWallb, *pEmbb, *pDecinb, *pWihb, *pWfcb, *pGx, *pHb;
    cudaGetSymbolAddress(&pU, g_U);
    cudaGetSymbolAddress(&pWallb, g_Wallb);
    cudaGetSymbolAddress(&pEmbb, g_embb);
    cudaGetSymbolAddress(&pDecinb, g_decinb);
    cudaGetSymbolAddress(&pWihb, g_Wihb);
    cudaGetSymbolAddress(&pWfcb, g_Wfcb);
    cudaGetSymbolAddress(&pGx, g_gx);
    cudaGetSymbolAddress(&pHb, g_hb);

    cudaFuncSetAttribute(gemmb, cudaFuncAttributeMaxDynamicSharedMemorySize, GEMMB_SMEM);
    cudaFuncSetAttribute(gemmbg, cudaFuncAttributeMaxDynamicSharedMemorySize, GEMMB_SMEM);
    cudaFuncSetAttribute(gemm_lsm, cudaFuncAttributeMaxDynamicSharedMemorySize, LSM_SMEM);
    cudaFuncSetAttribute(scan6d, cudaFuncAttributeMaxDynamicSharedMemorySize, SCAN_SMEM);

    prep<<<PREP_BLOCKS, 256>>>(word_ids, embed, Wih, w1, w2, w3, Wfc, enc);

    // conv taps: U_bf16[65536,768] = gather(embed_bf16) @ Wall_bf16^T
    gemmbg<<<dim3(768 / BBN, NROWS / BBM), 256, GEMMB_SMEM>>>(
        (const __nv_bfloat16*)pEmbb, (const __nv_bfloat16*)pWallb,
        (__nv_bfloat16*)pU, NROWS, 768, Dd, word_ids);
    conv_reduce<<<NSEGT, 192>>>(b1, b2, b3);

    // gates_x[8192,2048] = dec_in_bf16 @ W_ih_bf16^T
    gemmb<<<dim3(G4 / BBN, NSEGT / BBM), 256, GEMMB_SMEM>>>(
        (const __nv_bfloat16*)pDecinb, (const __nv_bfloat16*)pWihb,
        (float*)pGx, NSEGT, G4, DIN);

    scan6d<<<128, 512, SCAN_SMEM>>>(Whh);

    // fused logits + log_softmax (bf16 h, bf16 W_fc)
    gemm_lsm<<<NSEGT / LBM, 256, LSM_SMEM>>>(
        (const __nv_bfloat16*)pHb + (size_t)Bb * H2,
        (const __nv_bfloat16*)pWfcb, out);
}

// round 15
// speedup vs baseline: 1.1086x; 1.1086x over previous
#include <cuda_runtime.h>
#include <cuda_bf16.h>
#include <math.h>

// ---------------- problem constants ----------------
#define Bb    64
#define Ss    1024
#define Dd    256
#define Hh    256
#define H2    512
#define Ff    128
#define Tt    64
#define Ll    8
#define NSEG  128
#define DIN   1152
#define G4    2048           // 4 * H2
#define NROWS 65536          // B * S
#define NSEGT 8192           // B * NSEG
#define Vv    50000

// ---------------- scratch (static device, no allocs) ----------------
__device__ __nv_bfloat16 g_decinb[NSEGT * DIN];          // bf16 dec_in
__device__ __nv_bfloat16 g_U[(size_t)NROWS * 768];       // bf16 conv taps
__device__ __nv_bfloat16 g_Wallb[768 * Dd];              // bf16 stacked conv W
__device__ __nv_bfloat16 g_embb[(size_t)Vv * Dd];        // bf16 embed table
__device__ __nv_bfloat16 g_Wihb[(size_t)G4 * DIN];       // bf16 W_ih
__device__ __nv_bfloat16 g_Wfcb[Tt * H2];                // bf16 W_fc
__device__ float g_gx[(size_t)NSEGT * G4];
__device__ __nv_bfloat16 g_hb[(size_t)129 * Bb * H2];    // bf16 h
__device__ unsigned g_bar2[2];

// ---------------- helpers ----------------
__device__ __forceinline__ float sigmf(float x) { return 1.f / (1.f + __expf(-x)); }
__device__ __forceinline__ float tanhfast(float x) { return 2.f / (1.f + __expf(-2.f * x)) - 1.f; }
__device__ __forceinline__ unsigned packbf(float lo, float hi) {
    unsigned d;
    asm("cvt.rn.bf16x2.f32 %0, %1, %2;" : "=r"(d) : "f"(hi), "f"(lo));
    return d;
}
__device__ __forceinline__ float bflo(unsigned u) { return __uint_as_float(u << 16); }
__device__ __forceinline__ float bfhi(unsigned u) { return __uint_as_float(u & 0xffff0000u); }

#define MMA_BF16(acc, a0, a1, a2, a3, b0, b1)                                  \
    asm("mma.sync.aligned.m16n8k16.row.col.f32.bf16.bf16.f32 "                 \
        "{%0,%1,%2,%3},{%4,%5,%6,%7},{%8,%9},{%0,%1,%2,%3};"                   \
        : "+f"(acc[0]), "+f"(acc[1]), "+f"(acc[2]), "+f"(acc[3])               \
        : "r"(a0), "r"(a1), "r"(a2), "r"(a3), "r"(b0), "r"(b1))

#define LDSM_X4(r0, r1, r2, r3, addr)                                          \
    asm volatile("ldmatrix.sync.aligned.m8n8.x4.shared.b16 {%0,%1,%2,%3}, [%4];" \
                 : "=r"(r0), "=r"(r1), "=r"(r2), "=r"(r3) : "r"(addr))

#define CP_ASYNC16(dst, src)                                                   \
    asm volatile("cp.async.cg.shared.global [%0], [%1], 16;\n" ::              \
                 "r"(dst), "l"(src))

// ================= 128x128 bf16 GEMM (gates): C fp32 = A @ B^T =============
#define BBM 128
#define BBN 128
#define BBK 64
#define GEMMB_SMEM (2 * (BBM + BBN) * 144)   // 73728 B

__global__ __launch_bounds__(256, 2) void gemmb(
    const __nv_bfloat16* __restrict__ A, const __nv_bfloat16* __restrict__ Bw,
    float* __restrict__ C, int M, int N, int K)
{
    extern __shared__ unsigned short bsm[];

    int tid = threadIdx.x;
    int mBase = blockIdx.y * BBM, nBase = blockIdx.x * BBN;

    int w = tid >> 5, lane = tid & 31;
    int grp = lane >> 2, tig = lane & 3;
    int wm = w & 1, wn = w >> 1;       // 2x4 warp grid, warp tile 64x32

    unsigned smbase = (unsigned)__cvta_generic_to_shared(bsm);
    unsigned bbase = smbase + 2 * BBM * 144;

    unsigned aAddr0 = smbase + (unsigned)((wm * 64 + (lane & 15)) * 144 + ((lane >> 4) << 4));
    unsigned bAddr0 = bbase + (unsigned)((wn * 32 + (lane & 15)) * 144 + ((lane >> 4) << 4));

    float acc[4][4][4];
#pragma unroll
    for (int mt = 0; mt < 4; mt++)
#pragma unroll
        for (int nt = 0; nt < 4; nt++)
#pragma unroll
            for (int i = 0; i < 4; i++) acc[mt][nt][i] = 0.f;

    int nkt = K / BBK;

#define BLOAD(s, kt) do {                                                       \
        int koff = (kt) * BBK;                                                  \
        _Pragma("unroll")                                                       \
        for (int i = 0; i < 4; i++) {                                           \
            int cid = tid + i * 256;                                            \
            int row = cid >> 3, ch = cid & 7;                                   \
            const __nv_bfloat16* src = A + (size_t)(mBase + row) * K + koff + ch * 8; \
            unsigned dst = smbase + (unsigned)(((s) * BBM + row) * 144 + ch * 16);    \
            CP_ASYNC16(dst, src);                                               \
        }                                                                       \
        _Pragma("unroll")                                                       \
        for (int i = 0; i < 4; i++) {                                           \
            int cid = tid + i * 256;                                            \
            int row = cid >> 3, ch = cid & 7;                                   \
            const __nv_bfloat16* src = Bw + (size_t)(nBase + row) * K + koff + ch * 8; \
            unsigned dst = bbase + (unsigned)(((s) * BBN + row) * 144 + ch * 16);     \
            CP_ASYNC16(dst, src);                                               \
        }                                                                       \
        asm volatile("cp.async.commit_group;\n");                               \
    } while (0)

    BLOAD(0, 0);

    for (int kt = 0; kt < nkt; kt++) {
        int s = kt & 1;
        if (kt + 1 < nkt) {
            BLOAD((kt + 1) & 1, kt + 1);
            asm volatile("cp.async.wait_group 1;\n" ::: "memory");
        } else {
            asm volatile("cp.async.wait_group 0;\n" ::: "memory");
        }
        __syncthreads();

        unsigned aS = aAddr0 + (unsigned)(s * BBM * 144);
        unsigned bS = bAddr0 + (unsigned)(s * BBN * 144);
#pragma unroll
        for (int kc = 0; kc < 4; kc++) {
            unsigned kb = kc * 32;
            unsigned bfr[2][4];
#pragma unroll
            for (int ntp = 0; ntp < 2; ntp++)
                LDSM_X4(bfr[ntp][0], bfr[ntp][1], bfr[ntp][2], bfr[ntp][3],
                        bS + ntp * (16 * 144) + kb);
#pragma unroll
            for (int mt = 0; mt < 4; mt++) {
                unsigned a0, a1, a2, a3;
                LDSM_X4(a0, a1, a2, a3, aS + mt * (16 * 144) + kb);
                MMA_BF16(acc[mt][0], a0, a1, a2, a3, bfr[0][0], bfr[0][2]);
                MMA_BF16(acc[mt][1], a0, a1, a2, a3, bfr[0][1], bfr[0][3]);
                MMA_BF16(acc[mt][2], a0, a1, a2, a3, bfr[1][0], bfr[1][2]);
                MMA_BF16(acc[mt][3], a0, a1, a2, a3, bfr[1][1], bfr[1][3]);
            }
        }
        __syncthreads();
    }

#pragma unroll
    for (int mt = 0; mt < 4; mt++) {
        int row0 = mBase + wm * 64 + mt * 16 + grp;
#pragma unroll
        for (int nt = 0; nt < 4; nt++) {
            int col = nBase + wn * 32 + nt * 8 + tig * 2;
            *(float2*)&C[(size_t)row0 * N + col] = make_float2(acc[mt][nt][0], acc[mt][nt][1]);
            *(float2*)&C[(size_t)(row0 + 8) * N + col] = make_float2(acc[mt][nt][2], acc[mt][nt][3]);
        }
    }
}

// ================= gathered bf16 GEMM, bf16 out (conv taps) =================
__global__ __launch_bounds__(256, 2) void gemmbg(
    const __nv_bfloat16* __restrict__ A, const __nv_bfloat16* __restrict__ Bw,
    __nv_bfloat16* __restrict__ C, int M, int N, int K,
    const int* __restrict__ gather)
{
    extern __shared__ unsigned short bsm[];
    __shared__ int rows_s[BBM];

    int tid = threadIdx.x;
    int mBase = blockIdx.y * BBM, nBase = blockIdx.x * BBN;
    if (tid < BBM) rows_s[tid] = gather[mBase + tid];
    __syncthreads();

    int w = tid >> 5, lane = tid & 31;
    int grp = lane >> 2, tig = lane & 3;
    int wm = w & 1, wn = w >> 1;

    unsigned smbase = (unsigned)__cvta_generic_to_shared(bsm);
    unsigned bbase = smbase + 2 * BBM * 144;

    unsigned aAddr0 = smbase + (unsigned)((wm * 64 + (lane & 15)) * 144 + ((lane >> 4) << 4));
    unsigned bAddr0 = bbase + (unsigned)((wn * 32 + (lane & 15)) * 144 + ((lane >> 4) << 4));

    float acc[4][4][4];
#pragma unroll
    for (int mt = 0; mt < 4; mt++)
#pragma unroll
        for (int nt = 0; nt < 4; nt++)
#pragma unroll
            for (int i = 0; i < 4; i++) acc[mt][nt][i] = 0.f;

    int nkt = K / BBK;

#define BGLOAD(s, kt) do {                                                      \
        int koff = (kt) * BBK;                                                  \
        _Pragma("unroll")                                                       \
        for (int i = 0; i < 4; i++) {                                           \
            int cid = tid + i * 256;                                            \
            int row = cid >> 3, ch = cid & 7;                                   \
            const __nv_bfloat16* src = A + (size_t)rows_s[row] * K + koff + ch * 8;   \
            unsigned dst = smbase + (unsigned)(((s) * BBM + row) * 144 + ch * 16);    \
            CP_ASYNC16(dst, src);                                               \
        }                                                                       \
        _Pragma("unroll")                                                       \
        for (int i = 0; i < 4; i++) {                                           \
            int cid = tid + i * 256;                                            \
            int row = cid >> 3, ch = cid & 7;                                   \
            const __nv_bfloat16* src = Bw + (size_t)(nBase + row) * K + koff + ch * 8; \
            unsigned dst = bbase + (unsigned)(((s) * BBN + row) * 144 + ch * 16);     \
            CP_ASYNC16(dst, src);                                               \
        }                                                                       \
        asm volatile("cp.async.commit_group;\n");                               \
    } while (0)

    BGLOAD(0, 0);

    for (int kt = 0; kt < nkt; kt++) {
        int s = kt & 1;
        if (kt + 1 < nkt) {
            BGLOAD((kt + 1) & 1, kt + 1);
            asm volatile("cp.async.wait_group 1;\n" ::: "memory");
        } else {
            asm volatile("cp.async.wait_group 0;\n" ::: "memory");
        }
        __syncthreads();

        unsigned aS = aAddr0 + (unsigned)(s * BBM * 144);
        unsigned bS = bAddr0 + (unsigned)(s * BBN * 144);
#pragma unroll
        for (int kc = 0; kc < 4; kc++) {
            unsigned kb = kc * 32;
            unsigned bfr[2][4];
#pragma unroll
            for (int ntp = 0; ntp < 2; ntp++)
                LDSM_X4(bfr[ntp][0], bfr[ntp][1], bfr[ntp][2], bfr[ntp][3],
                        bS + ntp * (16 * 144) + kb);
#pragma unroll
            for (int mt = 0; mt < 4; mt++) {
                unsigned a0, a1, a2, a3;
                LDSM_X4(a0, a1, a2, a3, aS + mt * (16 * 144) + kb);
                MMA_BF16(acc[mt][0], a0, a1, a2, a3, bfr[0][0], bfr[0][2]);
                MMA_BF16(acc[mt][1], a0, a1, a2, a3, bfr[0][1], bfr[0][3]);
                MMA_BF16(acc[mt][2], a0, a1, a2, a3, bfr[1][0], bfr[1][2]);
                MMA_BF16(acc[mt][3], a0, a1, a2, a3, bfr[1][1], bfr[1][3]);
            }
        }
        __syncthreads();
    }

#pragma unroll
    for (int mt = 0; mt < 4; mt++) {
        int row0 = mBase + wm * 64 + mt * 16 + grp;
#pragma unroll
        for (int nt = 0; nt < 4; nt++) {
            int col = nBase + wn * 32 + nt * 8 + tig * 2;
            *(unsigned*)&C[(size_t)row0 * N + col] = packbf(acc[mt][nt][0], acc[mt][nt][1]);
            *(unsigned*)&C[(size_t)(row0 + 8) * N + col] = packbf(acc[mt][nt][2], acc[mt][nt][3]);
        }
    }
}

// ======== fused logits GEMM (bf16) + log_softmax + output permutation ========
#define LBM 128
#define LBN 64
#define LSM_SMEM (2 * (LBM + LBN) * 144)   // 55296 B

__global__ __launch_bounds__(256, 2) void gemm_lsm(
    const __nv_bfloat16* __restrict__ A, const __nv_bfloat16* __restrict__ Bw,
    float* __restrict__ out)
{
    extern __shared__ unsigned short bsm[];
    float* ls = (float*)bsm;

    int tid = threadIdx.x;
    int mBase = blockIdx.x * LBM;

    int w = tid >> 5, lane = tid & 31;
    int grp = lane >> 2, tig = lane & 3;
    int wm = w & 3, wn = w >> 2;

    unsigned smbase = (unsigned)__cvta_generic_to_shared(bsm);
    unsigned bbase = smbase + 2 * LBM * 144;

    unsigned aAddr0 = smbase + (unsigned)((wm * 32 + (lane & 15)) * 144 + ((lane >> 4) << 4));
    unsigned bAddr0 = bbase + (unsigned)((wn * 32 + (lane & 15)) * 144 + ((lane >> 4) << 4));

    float acc[2][4][4];
#pragma unroll
    for (int mt = 0; mt < 2; mt++)
#pragma unroll
        for (int nt = 0; nt < 4; nt++)
#pragma unroll
            for (int i = 0; i < 4; i++) acc[mt][nt][i] = 0.f;

#define LLOAD(s, kt) do {                                                       \
        int koff = (kt) * BBK;                                                  \
        _Pragma("unroll")                                                       \
        for (int i = 0; i < 4; i++) {                                           \
            int cid = tid + i * 256;                                            \
            int row = cid >> 3, ch = cid & 7;                                   \
            const __nv_bfloat16* src = A + (size_t)(mBase + row) * H2 + koff + ch * 8; \
            unsigned dst = smbase + (unsigned)(((s) * LBM + row) * 144 + ch * 16);     \
            CP_ASYNC16(dst, src);                                               \
        }                                                                       \
        _Pragma("unroll")                                                       \
        for (int i = 0; i < 2; i++) {                                           \
            int cid = tid + i * 256;                                            \
            int row = cid >> 3, ch = cid & 7;                                   \
            const __nv_bfloat16* src = Bw + (size_t)row * H2 + koff + ch * 8;   \
            unsigned dst = bbase + (unsigned)(((s) * LBN + row) * 144 + ch * 16);     \
            CP_ASYNC16(dst, src);                                               \
        }                                                                       \
        asm volatile("cp.async.commit_group;\n");                               \
    } while (0)

    LLOAD(0, 0);

    const int nkt = H2 / BBK;   // 8
    for (int kt = 0; kt < nkt; kt++) {
        int s = kt & 1;
        if (kt + 1 < nkt) {
            LLOAD((kt + 1) & 1, kt + 1);
            asm volatile("cp.async.wait_group 1;\n" ::: "memory");
        } else {
            asm volatile("cp.async.wait_group 0;\n" ::: "memory");
        }
        __syncthreads();

        unsigned aS = aAddr0 + (unsigned)(s * LBM * 144);
        unsigned bS = bAddr0 + (unsigned)(s * LBN * 144);
#pragma unroll
        for (int kc = 0; kc < 4; kc++) {
            unsigned kb = kc * 32;
            unsigned bfr[2][4];
#pragma unroll
            for (int ntp = 0; ntp < 2; ntp++)
                LDSM_X4(bfr[ntp][0], bfr[ntp][1], bfr[ntp][2], bfr[ntp][3],
                        bS + ntp * (16 * 144) + kb);
#pragma unroll
            for (int mt = 0; mt < 2; mt++) {
                unsigned a0, a1, a2, a3;
                LDSM_X4(a0, a1, a2, a3, aS + mt * (16 * 144) + kb);
                MMA_BF16(acc[mt][0], a0, a1, a2, a3, bfr[0][0], bfr[0][2]);
                MMA_BF16(acc[mt][1], a0, a1, a2, a3, bfr[0][1], bfr[0][3]);
                MMA_BF16(acc[mt][2], a0, a1, a2, a3, bfr[1][0], bfr[1][2]);
                MMA_BF16(acc[mt][3], a0, a1, a2, a3, bfr[1][1], bfr[1][3]);
            }
        }
        __syncthreads();
    }

#pragma unroll
    for (int mt = 0; mt < 2; mt++) {
        int row0 = wm * 32 + mt * 16 + grp;
#pragma unroll
        for (int nt = 0; nt < 4; nt++) {
            int col = wn * 32 + nt * 8 + tig * 2;
            *(float2*)&ls[row0 * 68 + col] = make_float2(acc[mt][nt][0], acc[mt][nt][1]);
            *(float2*)&ls[(row0 + 8) * 68 + col] = make_float2(acc[mt][nt][2], acc[mt][nt][3]);
        }
    }
    __syncthreads();

#pragma unroll 4
    for (int rr = 0; rr < 16; rr++) {
        int row = w * 16 + rr;
        float2 v = *(const float2*)&ls[row * 68 + lane * 2];
        float m = fmaxf(v.x, v.y);
#pragma unroll
        for (int o = 16; o; o >>= 1) m = fmaxf(m, __shfl_xor_sync(0xffffffffu, m, o));
        float s = expf(v.x - m) + expf(v.y - m);
#pragma unroll
        for (int o = 16; o; o >>= 1) s += __shfl_xor_sync(0xffffffffu, s, o);
        float lse = m + logf(s);
        int r = mBase + row;
        int t = r >> 6, bb = r & 63;
        *(float2*)&out[(size_t)(bb * NSEG + t) * Tt + lane * 2] =
            make_float2(v.x - lse, v.y - lse);
    }
}

// ------- fused prep: seg_feat | cvt_emb | cvt_wih | pack_wall | cvt_wfc | h0 -
#define PREP_S NSEGT
#define PREP_E 12500
#define PREP_W 2304
#define PREP_P 384
#define PREP_F 32
#define PREP_H 64
#define PREP_BLOCKS (PREP_S + PREP_E + PREP_W + PREP_P + PREP_F + PREP_H)

__global__ __launch_bounds__(256) void prep(
    const int* __restrict__ word_ids,
    const float* __restrict__ embed, const float* __restrict__ Wih,
    const float* __restrict__ w1, const float* __restrict__ w2,
    const float* __restrict__ w3, const float* __restrict__ Wfc,
    const float* __restrict__ enc)
{
    int bid = blockIdx.x, tid = threadIdx.x;
    if (bid < PREP_S) {
        int r = bid;
        int b = r >> 7, seg = r & 127;
        __shared__ int ids[8];
        if (tid < 8) ids[tid] = word_ids[b * Ss + seg * Ll + tid];
        __syncthreads();
        {
            float s = 0.f;
#pragma unroll
            for (int t = 0; t < 8; t++) s += embed[(size_t)ids[t] * Dd + tid];
            g_decinb[(size_t)r * DIN + tid] = __float2bfloat16(s * 0.125f);
        }
        for (int k = tid; k < H2; k += 256) {
            float s = 0.f;
#pragma unroll
            for (int t = 0; t < 8; t++) s += enc[(size_t)(b * Ss + seg * Ll + t) * H2 + k];
            g_decinb[(size_t)r * DIN + Dd + k] = __float2bfloat16(s * 0.125f);
        }
        return;
    }
    bid -= PREP_S;
    if (bid < PREP_E) {
        size_t i = ((size_t)bid * 256 + tid) * 4;
        float4 v = *(const float4*)(embed + i);
        *(uint2*)((unsigned short*)g_embb + i) =
            make_uint2(packbf(v.x, v.y), packbf(v.z, v.w));
        return;
    }
    bid -= PREP_E;
    if (bid < PREP_W) {
        size_t i = ((size_t)bid * 256 + tid) * 4;
        float4 v = *(const float4*)(Wih + i);
        *(uint2*)((unsigned short*)g_Wihb + i) =
            make_uint2(packbf(v.x, v.y), packbf(v.z, v.w));
        return;
    }
    bid -= PREP_W;
    if (bid < PREP_P) {
        int n = bid * 2 + (tid >> 7);
        int k = tid & 127;
        const float* src;
        if (n < 128)       src = w1 + n * Dd;
        else if (n < 384) { int m = n - 128; src = w2 + ((m & 127) * 2 + (m >> 7)) * Dd; }
        else              { int m = n - 384; src = w3 + ((m & 127) * 3 + (m >> 7)) * Dd; }
        *(unsigned*)&g_Wallb[n * Dd + k * 2] = packbf(src[k * 2], src[k * 2 + 1]);
        return;
    }
    bid -= PREP_P;
    if (bid < PREP_F) {
        size_t i = ((size_t)bid * 256 + tid) * 4;
        float4 v = *(const float4*)(Wfc + i);
        *(uint2*)((unsigned short*)g_Wfcb + i) =
            make_uint2(packbf(v.x, v.y), packbf(v.z, v.w));
        return;
    }
    bid -= PREP_F;
    {
        if (bid == 0 && tid < 2) g_bar2[tid] = 0;
        int b = bid;
        for (int j = tid; j < H2; j += 256) {
            float v = (j < Hh) ? enc[(size_t)(b * Ss + Ss - 1) * H2 + j]
                               : enc[(size_t)(b * Ss) * H2 + j];
            g_hb[(size_t)b * H2 + j] = __float2bfloat16(v);
        }
    }
}

// ---------------- conv tap-sum + relu + maxpool (vectorized bf16x2) ----------
__global__ __launch_bounds__(192) void conv_reduce(
    const float* __restrict__ b1, const float* __restrict__ b2, const float* __restrict__ b3)
{
    int r = blockIdx.x, tid = threadIdx.x;
    const unsigned* U = (const unsigned*)(g_U + (size_t)r * 8 * 768);
    unsigned* d = (unsigned*)(g_decinb + (size_t)r * DIN + 768);

    int which = tid >> 6, p = tid & 63;
    float mx = -1e30f, my = -1e30f;

    if (which == 0) {
#pragma unroll
        for (int t = 0; t < 8; t++) {
            unsigned u = U[t * 384 + p];
            mx = fmaxf(mx, bflo(u)); my = fmaxf(my, bfhi(u));
        }
        mx += b1[p * 2]; my += b1[p * 2 + 1];
    } else if (which == 1) {
#pragma unroll
        for (int t = 0; t < 7; t++) {
            unsigned u0 = U[t * 384 + 64 + p];
            unsigned u1 = U[(t + 1) * 384 + 128 + p];
            mx = fmaxf(mx, bflo(u0) + bflo(u1));
            my = fmaxf(my, bfhi(u0) + bfhi(u1));
        }
        mx += b2[p * 2]; my += b2[p * 2 + 1];
    } else {
#pragma unroll
        for (int t = 0; t < 6; t++) {
            unsigned u0 = U[t * 384 + 192 + p];
            unsigned u1 = U[(t + 1) * 384 + 256 + p];
            unsigned u2 = U[(t + 2) * 384 + 320 + p];
            mx = fmaxf(mx, bflo(u0) + bflo(u1) + bflo(u2));
            my = fmaxf(my, bfhi(u0) + bfhi(u1) + bfhi(u2));
        }
        mx += b3[p * 2]; my += b3[p * 2 + 1];
    }
    d[which * 64 + p] = packbf(fmaxf(mx, 0.f), fmaxf(my, 0.f));
}

// ================= bf16 scan (R6/R9/R11-proven scan6) =================
#define SCP 520
#define SCAN_SMEM (32 * SCP * 2 + 8 * 32 * 34 * 4)   // 68096 B

__global__ __launch_bounds__(512, 1) void scan6(const float* __restrict__ Whh)
{
    extern __shared__ unsigned ssm[];
    __nv_bfloat16* hA = (__nv_bfloat16*)ssm;                 // [32][520]
    float* pbuf = (float*)((char*)ssm + 32 * SCP * 2);       // [8][32][34]

    int tid = threadIdx.x;
    int lane = tid & 31, w = tid >> 5;
    int grp = lane >> 2, tig = lane & 3;
    int mt = w & 1, kq = w >> 1;
    int cid = blockIdx.x;
    int bg = cid & 1;
    int j0 = (cid >> 1) * 8;

    unsigned bw[4][4][2];
#pragma unroll
    for (int nt = 0; nt < 4; nt++) {
        const float* wr = Whh + (size_t)(nt * H2 + j0 + grp) * H2 + kq * 64;
#pragma unroll
        for (int kc = 0; kc < 4; kc++) {
            const float* p = wr + kc * 16 + tig * 2;
            bw[nt][kc][0] = packbf(p[0], p[1]);
            bw[nt][kc][1] = packbf(p[8], p[9]);
        }
    }

    const __nv_bfloat16* ghb = g_hb;
    unsigned* pcount = &g_bar2[bg];

    float c_st = 0.f;
    int b_hat = tid >> 3, jj = tid & 7;     // epilogue item (tid<256)
    int row_global = bg * 32 + b_hat;
    size_t gx_base = (size_t)(row_global * NSEG) * G4 + (size_t)(j0 + jj);

    unsigned hA_u32 = (unsigned)__cvta_generic_to_shared(hA);
    unsigned dstbase = hA_u32 + (unsigned)((mt * 16) * (SCP * 2) + kq * 128);
    unsigned ldbase = hA_u32 + (unsigned)((mt * 16 + (lane & 15)) * (SCP * 2)
                                          + kq * 128 + ((lane >> 4) << 4));

    float gxi = 0.f, gxf = 0.f, gxg = 0.f, gxq = 0.f;
    if (tid < 256) {
        gxi = __ldg(&g_gx[gx_base]);
        gxf = __ldg(&g_gx[gx_base + 512]);
        gxg = __ldg(&g_gx[gx_base + 1024]);
        gxq = __ldg(&g_gx[gx_base + 1536]);
    }

    for (int t = 0; t < NSEG; t++) {
        {
            const __nv_bfloat16* src = ghb + (size_t)t * Bb * H2
                                     + (size_t)(bg * 32 + mt * 16) * H2 + kq * 64;
#pragma unroll
            for (int i = 0; i < 4; i++) {
                int c = lane + 32 * i;
                int r = c >> 3, ch = c & 7;
                CP_ASYNC16(dstbase + (unsigned)(r * (SCP * 2) + ch * 16),
                           src + r * H2 + ch * 8);
            }
            asm volatile("cp.async.commit_group;\n");
        }
        asm volatile("cp.async.wait_group 0;\n" ::: "memory");
        __syncwarp();

        float acc[4][4];
#pragma unroll
        for (int nt = 0; nt < 4; nt++)
#pragma unroll
            for (int i = 0; i < 4; i++) acc[nt][i] = 0.f;
#pragma unroll
        for (int kc = 0; kc < 4; kc++) {
            unsigned a0, a1, a2, a3;
            LDSM_X4(a0, a1, a2, a3, ldbase + kc * 32);
#pragma unroll
            for (int nt = 0; nt < 4; nt++)
                MMA_BF16(acc[nt], a0, a1, a2, a3, bw[nt][kc][0], bw[nt][kc][1]);
        }
        {
            float* pb = pbuf + kq * (32 * 34);
            int row = mt * 16 + grp;
#pragma unroll
            for (int nt = 0; nt < 4; nt++) {
                int c0 = nt * 8 + tig * 2;
                pb[row * 34 + c0]           = acc[nt][0];
                pb[row * 34 + c0 + 1]       = acc[nt][1];
                pb[(row + 8) * 34 + c0]     = acc[nt][2];
                pb[(row + 8) * 34 + c0 + 1] = acc[nt][3];
            }
        }
        __syncthreads();

        if (tid < 256) {
            float gsum[4];
#pragma unroll
            for (int q = 0; q < 4; q++) {
                int col = q * 8 + jj;
                float s = 0.f;
#pragma unroll
                for (int k = 0; k < 8; k++) s += pbuf[k * (32 * 34) + b_hat * 34 + col];
                gsum[q] = s;
            }
            float gi = gsum[0] + gxi;
            float gf = gsum[1] + gxf;
            float gg = gsum[2] + gxg;
            float go = gsum[3] + gxq;
            c_st = sigmf(gf) * c_st + sigmf(gi) * tanhfast(gg);
            float h = sigmf(go) * tanhfast(c_st);
            size_t ho = (size_t)(t + 1) * Bb * H2 + (size_t)row_global * H2 + j0 + jj;
            g_hb[ho] = __float2bfloat16(h);

            if (t + 1 < NSEG) {
                size_t gxo = gx_base + (size_t)(t + 1) * G4;
                gxi = __ldg(&g_gx[gxo]);
                gxf = __ldg(&g_gx[gxo + 512]);
                gxg = __ldg(&g_gx[gxo + 1024]);
                gxq = __ldg(&g_gx[gxo + 1536]);
            }
        }

        __syncthreads();
        if (t + 1 < NSEG) {
            if (tid == 0) {
                unsigned one = 1;
                asm volatile("red.release.gpu.global.add.u32 [%0], %1;"
                             :: "l"(pcount), "r"(one) : "memory");
                unsigned target = 64u * (unsigned)(t + 1);
                unsigned cur;
                do {
                    asm volatile("ld.acquire.gpu.global.u32 %0, [%1];"
                                 : "=r"(cur) : "l"(pcount));
                } while (cur < target);
            }
            __syncthreads();
        }
    }
}

// ---------------- launcher ----------------
extern "C" void kernel_launch(void* const* d_in, const int* in_sizes, int n_in,
                              void* d_out, int out_size)
{
    const int*   word_ids = (const int*)d_in[0];
    const float* embed    = (const float*)d_in[1];
    const float* enc      = (const float*)d_in[2];
    const float* w1       = (const float*)d_in[3];
    const float* b1       = (const float*)d_in[4];
    const float* w2       = (const float*)d_in[5];
    const float* b2       = (const float*)d_in[6];
    const float* w3       = (const float*)d_in[7];
    const float* b3       = (const float*)d_in[8];
    const float* Wih      = (const float*)d_in[9];
    const float* Whh      = (const float*)d_in[10];
    const float* Wfc      = (const float*)d_in[11];
    float* out = (float*)d_out;

    void *pU, *pWallb, *pEmbb, *pDecinb, *pWihb, *pWfcb, *pGx, *pHb;
    cudaGetSymbolAddress(&pU, g_U);
    cudaGetSymbolAddress(&pWallb, g_Wallb);
    cudaGetSymbolAddress(&pEmbb, g_embb);
    cudaGetSymbolAddress(&pDecinb, g_decinb);
    cudaGetSymbolAddress(&pWihb, g_Wihb);
    cudaGetSymbolAddress(&pWfcb, g_Wfcb);
    cudaGetSymbolAddress(&pGx, g_gx);
    cudaGetSymbolAddress(&pHb, g_hb);

    cudaFuncSetAttribute(gemmb, cudaFuncAttributeMaxDynamicSharedMemorySize, GEMMB_SMEM);
    cudaFuncSetAttribute(gemmbg, cudaFuncAttributeMaxDynamicSharedMemorySize, GEMMB_SMEM);
    cudaFuncSetAttribute(gemm_lsm, cudaFuncAttributeMaxDynamicSharedMemorySize, LSM_SMEM);
    cudaFuncSetAttribute(scan6, cudaFuncAttributeMaxDynamicSharedMemorySize, SCAN_SMEM);

    prep<<<PREP_BLOCKS, 256>>>(word_ids, embed, Wih, w1, w2, w3, Wfc, enc);

    // conv taps: U_bf16[65536,768] = gather(embed_bf16) @ Wall_bf16^T
    gemmbg<<<dim3(768 / BBN, NROWS / BBM), 256, GEMMB_SMEM>>>(
        (const __nv_bfloat16*)pEmbb, (const __nv_bfloat16*)pWallb,
        (__nv_bfloat16*)pU, NROWS, 768, Dd, word_ids);
    conv_reduce<<<NSEGT, 192>>>(b1, b2, b3);

    // gates_x[8192,2048] = dec_in_bf16 @ W_ih_bf16^T
    gemmb<<<dim3(G4 / BBN, NSEGT / BBM), 256, GEMMB_SMEM>>>(
        (const __nv_bfloat16*)pDecinb, (const __nv_bfloat16*)pWihb,
        (float*)pGx, NSEGT, G4, DIN);

    scan6<<<128, 512, SCAN_SMEM>>>(Whh);

    // fused logits + log_softmax (bf16 h, bf16 W_fc)
    gemm_lsm<<<NSEGT / LBM, 256, LSM_SMEM>>>(
        (const __nv_bfloat16*)pHb + (size_t)Bb * H2,
        (const __nv_bfloat16*)pWfcb, out);
}

// round 16
// speedup vs baseline: 1.1510x; 1.0382x over previous
#include <cuda_runtime.h>
#include <cuda_bf16.h>
#include <math.h>

// ---------------- problem constants ----------------
#define Bb    64
#define Ss    1024
#define Dd    256
#define Hh    256
#define H2    512
#define Ff    128
#define Tt    64
#define Ll    8
#define NSEG  128
#define DIN   1152
#define G4    2048           // 4 * H2
#define NROWS 65536          // B * S
#define NSEGT 8192           // B * NSEG
#define Vv    50000

// ---------------- scratch (static device, no allocs) ----------------
__device__ __nv_bfloat16 g_decinb[NSEGT * DIN];          // bf16 dec_in
__device__ __nv_bfloat16 g_U[(size_t)NROWS * 768];       // bf16 conv taps (per-vocab; 65536-row slack)
__device__ __nv_bfloat16 g_Wallb[768 * Dd];              // bf16 stacked conv W
__device__ __nv_bfloat16 g_embb[(size_t)Vv * Dd];        // bf16 embed table
__device__ __nv_bfloat16 g_Wihb[(size_t)G4 * DIN];       // bf16 W_ih
__device__ __nv_bfloat16 g_Wfcb[Tt * H2];                // bf16 W_fc
__device__ float g_gx[(size_t)NSEGT * G4];
__device__ __nv_bfloat16 g_hb[(size_t)129 * Bb * H2];    // bf16 h
__device__ unsigned g_bar2[2];

// ---------------- helpers ----------------
__device__ __forceinline__ float sigmf(float x) { return 1.f / (1.f + __expf(-x)); }
__device__ __forceinline__ float tanhfast(float x) { return 2.f / (1.f + __expf(-2.f * x)) - 1.f; }
__device__ __forceinline__ unsigned packbf(float lo, float hi) {
    unsigned d;
    asm("cvt.rn.bf16x2.f32 %0, %1, %2;" : "=r"(d) : "f"(hi), "f"(lo));
    return d;
}
__device__ __forceinline__ float bflo(unsigned u) { return __uint_as_float(u << 16); }
__device__ __forceinline__ float bfhi(unsigned u) { return __uint_as_float(u & 0xffff0000u); }

#define MMA_BF16(acc, a0, a1, a2, a3, b0, b1)                                  \
    asm("mma.sync.aligned.m16n8k16.row.col.f32.bf16.bf16.f32 "                 \
        "{%0,%1,%2,%3},{%4,%5,%6,%7},{%8,%9},{%0,%1,%2,%3};"                   \
        : "+f"(acc[0]), "+f"(acc[1]), "+f"(acc[2]), "+f"(acc[3])               \
        : "r"(a0), "r"(a1), "r"(a2), "r"(a3), "r"(b0), "r"(b1))

#define LDSM_X4(r0, r1, r2, r3, addr)                                          \
    asm volatile("ldmatrix.sync.aligned.m8n8.x4.shared.b16 {%0,%1,%2,%3}, [%4];" \
                 : "=r"(r0), "=r"(r1), "=r"(r2), "=r"(r3) : "r"(addr))

#define CP_ASYNC16(dst, src)                                                   \
    asm volatile("cp.async.cg.shared.global [%0], [%1], 16;\n" ::              \
                 "r"(dst), "l"(src))

// ================= 128x128 bf16 GEMM (gates): C fp32 = A @ B^T =============
#define BBM 128
#define BBN 128
#define BBK 64
#define GEMMB_SMEM (2 * (BBM + BBN) * 144)   // 73728 B

__global__ __launch_bounds__(256, 2) void gemmb(
    const __nv_bfloat16* __restrict__ A, const __nv_bfloat16* __restrict__ Bw,
    float* __restrict__ C, int M, int N, int K)
{
    extern __shared__ unsigned short bsm[];

    int tid = threadIdx.x;
    int mBase = blockIdx.y * BBM, nBase = blockIdx.x * BBN;

    int w = tid >> 5, lane = tid & 31;
    int grp = lane >> 2, tig = lane & 3;
    int wm = w & 1, wn = w >> 1;       // 2x4 warp grid, warp tile 64x32

    unsigned smbase = (unsigned)__cvta_generic_to_shared(bsm);
    unsigned bbase = smbase + 2 * BBM * 144;

    unsigned aAddr0 = smbase + (unsigned)((wm * 64 + (lane & 15)) * 144 + ((lane >> 4) << 4));
    unsigned bAddr0 = bbase + (unsigned)((wn * 32 + (lane & 15)) * 144 + ((lane >> 4) << 4));

    float acc[4][4][4];
#pragma unroll
    for (int mt = 0; mt < 4; mt++)
#pragma unroll
        for (int nt = 0; nt < 4; nt++)
#pragma unroll
            for (int i = 0; i < 4; i++) acc[mt][nt][i] = 0.f;

    int nkt = K / BBK;

#define BLOAD(s, kt) do {                                                       \
        int koff = (kt) * BBK;                                                  \
        _Pragma("unroll")                                                       \
        for (int i = 0; i < 4; i++) {                                           \
            int cid = tid + i * 256;                                            \
            int row = cid >> 3, ch = cid & 7;                                   \
            const __nv_bfloat16* src = A + (size_t)(mBase + row) * K + koff + ch * 8; \
            unsigned dst = smbase + (unsigned)(((s) * BBM + row) * 144 + ch * 16);    \
            CP_ASYNC16(dst, src);                                               \
        }                                                                       \
        _Pragma("unroll")                                                       \
        for (int i = 0; i < 4; i++) {                                           \
            int cid = tid + i * 256;                                            \
            int row = cid >> 3, ch = cid & 7;                                   \
            const __nv_bfloat16* src = Bw + (size_t)(nBase + row) * K + koff + ch * 8; \
            unsigned dst = bbase + (unsigned)(((s) * BBN + row) * 144 + ch * 16);     \
            CP_ASYNC16(dst, src);                                               \
        }                                                                       \
        asm volatile("cp.async.commit_group;\n");                               \
    } while (0)

    BLOAD(0, 0);

    for (int kt = 0; kt < nkt; kt++) {
        int s = kt & 1;
        if (kt + 1 < nkt) {
            BLOAD((kt + 1) & 1, kt + 1);
            asm volatile("cp.async.wait_group 1;\n" ::: "memory");
        } else {
            asm volatile("cp.async.wait_group 0;\n" ::: "memory");
        }
        __syncthreads();

        unsigned aS = aAddr0 + (unsigned)(s * BBM * 144);
        unsigned bS = bAddr0 + (unsigned)(s * BBN * 144);
#pragma unroll
        for (int kc = 0; kc < 4; kc++) {
            unsigned kb = kc * 32;
            unsigned bfr[2][4];
#pragma unroll
            for (int ntp = 0; ntp < 2; ntp++)
                LDSM_X4(bfr[ntp][0], bfr[ntp][1], bfr[ntp][2], bfr[ntp][3],
                        bS + ntp * (16 * 144) + kb);
#pragma unroll
            for (int mt = 0; mt < 4; mt++) {
                unsigned a0, a1, a2, a3;
                LDSM_X4(a0, a1, a2, a3, aS + mt * (16 * 144) + kb);
                MMA_BF16(acc[mt][0], a0, a1, a2, a3, bfr[0][0], bfr[0][2]);
                MMA_BF16(acc[mt][1], a0, a1, a2, a3, bfr[0][1], bfr[0][3]);
                MMA_BF16(acc[mt][2], a0, a1, a2, a3, bfr[1][0], bfr[1][2]);
                MMA_BF16(acc[mt][3], a0, a1, a2, a3, bfr[1][1], bfr[1][3]);
            }
        }
        __syncthreads();
    }

#pragma unroll
    for (int mt = 0; mt < 4; mt++) {
        int row0 = mBase + wm * 64 + mt * 16 + grp;
#pragma unroll
        for (int nt = 0; nt < 4; nt++) {
            int col = nBase + wn * 32 + nt * 8 + tig * 2;
            *(float2*)&C[(size_t)row0 * N + col] = make_float2(acc[mt][nt][0], acc[mt][nt][1]);
            *(float2*)&C[(size_t)(row0 + 8) * N + col] = make_float2(acc[mt][nt][2], acc[mt][nt][3]);
        }
    }
}

// ====== 128x128 bf16 GEMM over VOCAB, bf16 out (conv taps, row-clamped) ======
__global__ __launch_bounds__(256, 2) void gemmU(
    const __nv_bfloat16* __restrict__ A, const __nv_bfloat16* __restrict__ Bw,
    __nv_bfloat16* __restrict__ C, int M, int N, int K)
{
    extern __shared__ unsigned short bsm[];

    int tid = threadIdx.x;
    int mBase = blockIdx.y * BBM, nBase = blockIdx.x * BBN;

    int w = tid >> 5, lane = tid & 31;
    int grp = lane >> 2, tig = lane & 3;
    int wm = w & 1, wn = w >> 1;

    unsigned smbase = (unsigned)__cvta_generic_to_shared(bsm);
    unsigned bbase = smbase + 2 * BBM * 144;

    unsigned aAddr0 = smbase + (unsigned)((wm * 64 + (lane & 15)) * 144 + ((lane >> 4) << 4));
    unsigned bAddr0 = bbase + (unsigned)((wn * 32 + (lane & 15)) * 144 + ((lane >> 4) << 4));

    float acc[4][4][4];
#pragma unroll
    for (int mt = 0; mt < 4; mt++)
#pragma unroll
        for (int nt = 0; nt < 4; nt++)
#pragma unroll
            for (int i = 0; i < 4; i++) acc[mt][nt][i] = 0.f;

    int nkt = K / BBK;

#define ULOAD(s, kt) do {                                                       \
        int koff = (kt) * BBK;                                                  \
        _Pragma("unroll")                                                       \
        for (int i = 0; i < 4; i++) {                                           \
            int cid = tid + i * 256;                                            \
            int row = cid >> 3, ch = cid & 7;                                   \
            int ar = mBase + row; if (ar >= M) ar = M - 1;                      \
            const __nv_bfloat16* src = A + (size_t)ar * K + koff + ch * 8;      \
            unsigned dst = smbase + (unsigned)(((s) * BBM + row) * 144 + ch * 16);    \
            CP_ASYNC16(dst, src);                                               \
        }                                                                       \
        _Pragma("unroll")                                                       \
        for (int i = 0; i < 4; i++) {                                           \
            int cid = tid + i * 256;                                            \
            int row = cid >> 3, ch = cid & 7;                                   \
            const __nv_bfloat16* src = Bw + (size_t)(nBase + row) * K + koff + ch * 8; \
            unsigned dst = bbase + (unsigned)(((s) * BBN + row) * 144 + ch * 16);     \
            CP_ASYNC16(dst, src);                                               \
        }                                                                       \
        asm volatile("cp.async.commit_group;\n");                               \
    } while (0)

    ULOAD(0, 0);

    for (int kt = 0; kt < nkt; kt++) {
        int s = kt & 1;
        if (kt + 1 < nkt) {
            ULOAD((kt + 1) & 1, kt + 1);
            asm volatile("cp.async.wait_group 1;\n" ::: "memory");
        } else {
            asm volatile("cp.async.wait_group 0;\n" ::: "memory");
        }
        __syncthreads();

        unsigned aS = aAddr0 + (unsigned)(s * BBM * 144);
        unsigned bS = bAddr0 + (unsigned)(s * BBN * 144);
#pragma unroll
        for (int kc = 0; kc < 4; kc++) {
            unsigned kb = kc * 32;
            unsigned bfr[2][4];
#pragma unroll
            for (int ntp = 0; ntp < 2; ntp++)
                LDSM_X4(bfr[ntp][0], bfr[ntp][1], bfr[ntp][2], bfr[ntp][3],
                        bS + ntp * (16 * 144) + kb);
#pragma unroll
            for (int mt = 0; mt < 4; mt++) {
                unsigned a0, a1, a2, a3;
                LDSM_X4(a0, a1, a2, a3, aS + mt * (16 * 144) + kb);
                MMA_BF16(acc[mt][0], a0, a1, a2, a3, bfr[0][0], bfr[0][2]);
                MMA_BF16(acc[mt][1], a0, a1, a2, a3, bfr[0][1], bfr[0][3]);
                MMA_BF16(acc[mt][2], a0, a1, a2, a3, bfr[1][0], bfr[1][2]);
                MMA_BF16(acc[mt][3], a0, a1, a2, a3, bfr[1][1], bfr[1][3]);
            }
        }
        __syncthreads();
    }

#pragma unroll
    for (int mt = 0; mt < 4; mt++) {
        int row0 = mBase + wm * 64 + mt * 16 + grp;
#pragma unroll
        for (int nt = 0; nt < 4; nt++) {
            int col = nBase + wn * 32 + nt * 8 + tig * 2;
            *(unsigned*)&C[(size_t)row0 * N + col] = packbf(acc[mt][nt][0], acc[mt][nt][1]);
            *(unsigned*)&C[(size_t)(row0 + 8) * N + col] = packbf(acc[mt][nt][2], acc[mt][nt][3]);
        }
    }
}

// ======== fused logits GEMM (bf16) + log_softmax + output permutation ========
#define LBM 128
#define LBN 64
#define LSM_SMEM (2 * (LBM + LBN) * 144)   // 55296 B

__global__ __launch_bounds__(256, 2) void gemm_lsm(
    const __nv_bfloat16* __restrict__ A, const __nv_bfloat16* __restrict__ Bw,
    float* __restrict__ out)
{
    extern __shared__ unsigned short bsm[];
    float* ls = (float*)bsm;

    int tid = threadIdx.x;
    int mBase = blockIdx.x * LBM;

    int w = tid >> 5, lane = tid & 31;
    int grp = lane >> 2, tig = lane & 3;
    int wm = w & 3, wn = w >> 2;

    unsigned smbase = (unsigned)__cvta_generic_to_shared(bsm);
    unsigned bbase = smbase + 2 * LBM * 144;

    unsigned aAddr0 = smbase + (unsigned)((wm * 32 + (lane & 15)) * 144 + ((lane >> 4) << 4));
    unsigned bAddr0 = bbase + (unsigned)((wn * 32 + (lane & 15)) * 144 + ((lane >> 4) << 4));

    float acc[2][4][4];
#pragma unroll
    for (int mt = 0; mt < 2; mt++)
#pragma unroll
        for (int nt = 0; nt < 4; nt++)
#pragma unroll
            for (int i = 0; i < 4; i++) acc[mt][nt][i] = 0.f;

#define LLOAD(s, kt) do {                                                       \
        int koff = (kt) * BBK;                                                  \
        _Pragma("unroll")                                                       \
        for (int i = 0; i < 4; i++) {                                           \
            int cid = tid + i * 256;                                            \
            int row = cid >> 3, ch = cid & 7;                                   \
            const __nv_bfloat16* src = A + (size_t)(mBase + row) * H2 + koff + ch * 8; \
            unsigned dst = smbase + (unsigned)(((s) * LBM + row) * 144 + ch * 16);     \
            CP_ASYNC16(dst, src);                                               \
        }                                                                       \
        _Pragma("unroll")                                                       \
        for (int i = 0; i < 2; i++) {                                           \
            int cid = tid + i * 256;                                            \
            int row = cid >> 3, ch = cid & 7;                                   \
            const __nv_bfloat16* src = Bw + (size_t)row * H2 + koff + ch * 8;   \
            unsigned dst = bbase + (unsigned)(((s) * LBN + row) * 144 + ch * 16);     \
            CP_ASYNC16(dst, src);                                               \
        }                                                                       \
        asm volatile("cp.async.commit_group;\n");                               \
    } while (0)

    LLOAD(0, 0);

    const int nkt = H2 / BBK;   // 8
    for (int kt = 0; kt < nkt; kt++) {
        int s = kt & 1;
        if (kt + 1 < nkt) {
            LLOAD((kt + 1) & 1, kt + 1);
            asm volatile("cp.async.wait_group 1;\n" ::: "memory");
        } else {
            asm volatile("cp.async.wait_group 0;\n" ::: "memory");
        }
        __syncthreads();

        unsigned aS = aAddr0 + (unsigned)(s * LBM * 144);
        unsigned bS = bAddr0 + (unsigned)(s * LBN * 144);
#pragma unroll
        for (int kc = 0; kc < 4; kc++) {
            unsigned kb = kc * 32;
            unsigned bfr[2][4];
#pragma unroll
            for (int ntp = 0; ntp < 2; ntp++)
                LDSM_X4(bfr[ntp][0], bfr[ntp][1], bfr[ntp][2], bfr[ntp][3],
                        bS + ntp * (16 * 144) + kb);
#pragma unroll
            for (int mt = 0; mt < 2; mt++) {
                unsigned a0, a1, a2, a3;
                LDSM_X4(a0, a1, a2, a3, aS + mt * (16 * 144) + kb);
                MMA_BF16(acc[mt][0], a0, a1, a2, a3, bfr[0][0], bfr[0][2]);
                MMA_BF16(acc[mt][1], a0, a1, a2, a3, bfr[0][1], bfr[0][3]);
                MMA_BF16(acc[mt][2], a0, a1, a2, a3, bfr[1][0], bfr[1][2]);
                MMA_BF16(acc[mt][3], a0, a1, a2, a3, bfr[1][1], bfr[1][3]);
            }
        }
        __syncthreads();
    }

#pragma unroll
    for (int mt = 0; mt < 2; mt++) {
        int row0 = wm * 32 + mt * 16 + grp;
#pragma unroll
        for (int nt = 0; nt < 4; nt++) {
            int col = wn * 32 + nt * 8 + tig * 2;
            *(float2*)&ls[row0 * 68 + col] = make_float2(acc[mt][nt][0], acc[mt][nt][1]);
            *(float2*)&ls[(row0 + 8) * 68 + col] = make_float2(acc[mt][nt][2], acc[mt][nt][3]);
        }
    }
    __syncthreads();

#pragma unroll 4
    for (int rr = 0; rr < 16; rr++) {
        int row = w * 16 + rr;
        float2 v = *(const float2*)&ls[row * 68 + lane * 2];
        float m = fmaxf(v.x, v.y);
#pragma unroll
        for (int o = 16; o; o >>= 1) m = fmaxf(m, __shfl_xor_sync(0xffffffffu, m, o));
        float s = expf(v.x - m) + expf(v.y - m);
#pragma unroll
        for (int o = 16; o; o >>= 1) s += __shfl_xor_sync(0xffffffffu, s, o);
        float lse = m + logf(s);
        int r = mBase + row;
        int t = r >> 6, bb = r & 63;
        *(float2*)&out[(size_t)(bb * NSEG + t) * Tt + lane * 2] =
            make_float2(v.x - lse, v.y - lse);
    }
}

// ------- fused prep: seg_feat | cvt_emb | cvt_wih | pack_wall | cvt_wfc | h0 -
#define PREP_S NSEGT
#define PREP_E 12500
#define PREP_W 2304
#define PREP_P 384
#define PREP_F 32
#define PREP_H 64
#define PREP_BLOCKS (PREP_S + PREP_E + PREP_W + PREP_P + PREP_F + PREP_H)

__global__ __launch_bounds__(256) void prep(
    const int* __restrict__ word_ids,
    const float* __restrict__ embed, const float* __restrict__ Wih,
    const float* __restrict__ w1, const float* __restrict__ w2,
    const float* __restrict__ w3, const float* __restrict__ Wfc,
    const float* __restrict__ enc)
{
    int bid = blockIdx.x, tid = threadIdx.x;
    if (bid < PREP_S) {
        int r = bid;
        int b = r >> 7, seg = r & 127;
        __shared__ int ids[8];
        if (tid < 8) ids[tid] = word_ids[b * Ss + seg * Ll + tid];
        __syncthreads();
        {
            float s = 0.f;
#pragma unroll
            for (int t = 0; t < 8; t++) s += embed[(size_t)ids[t] * Dd + tid];
            g_decinb[(size_t)r * DIN + tid] = __float2bfloat16(s * 0.125f);
        }
        for (int k = tid; k < H2; k += 256) {
            float s = 0.f;
#pragma unroll
            for (int t = 0; t < 8; t++) s += enc[(size_t)(b * Ss + seg * Ll + t) * H2 + k];
            g_decinb[(size_t)r * DIN + Dd + k] = __float2bfloat16(s * 0.125f);
        }
        return;
    }
    bid -= PREP_S;
    if (bid < PREP_E) {
        size_t i = ((size_t)bid * 256 + tid) * 4;
        float4 v = *(const float4*)(embed + i);
        *(uint2*)((unsigned short*)g_embb + i) =
            make_uint2(packbf(v.x, v.y), packbf(v.z, v.w));
        return;
    }
    bid -= PREP_E;
    if (bid < PREP_W) {
        size_t i = ((size_t)bid * 256 + tid) * 4;
        float4 v = *(const float4*)(Wih + i);
        *(uint2*)((unsigned short*)g_Wihb + i) =
            make_uint2(packbf(v.x, v.y), packbf(v.z, v.w));
        return;
    }
    bid -= PREP_W;
    if (bid < PREP_P) {
        int n = bid * 2 + (tid >> 7);
        int k = tid & 127;
        const float* src;
        if (n < 128)       src = w1 + n * Dd;
        else if (n < 384) { int m = n - 128; src = w2 + ((m & 127) * 2 + (m >> 7)) * Dd; }
        else              { int m = n - 384; src = w3 + ((m & 127) * 3 + (m >> 7)) * Dd; }
        *(unsigned*)&g_Wallb[n * Dd + k * 2] = packbf(src[k * 2], src[k * 2 + 1]);
        return;
    }
    bid -= PREP_P;
    if (bid < PREP_F) {
        size_t i = ((size_t)bid * 256 + tid) * 4;
        float4 v = *(const float4*)(Wfc + i);
        *(uint2*)((unsigned short*)g_Wfcb + i) =
            make_uint2(packbf(v.x, v.y), packbf(v.z, v.w));
        return;
    }
    bid -= PREP_F;
    {
        if (bid == 0 && tid < 2) g_bar2[tid] = 0;
        int b = bid;
        for (int j = tid; j < H2; j += 256) {
            float v = (j < Hh) ? enc[(size_t)(b * Ss + Ss - 1) * H2 + j]
                               : enc[(size_t)(b * Ss) * H2 + j];
            g_hb[(size_t)b * H2 + j] = __float2bfloat16(v);
        }
    }
}

// -------- conv tap-sum + relu + maxpool (vocab-gathered, bf16x2) --------
__global__ __launch_bounds__(192) void conv_reduce(
    const int* __restrict__ word_ids,
    const float* __restrict__ b1, const float* __restrict__ b2, const float* __restrict__ b3)
{
    int r = blockIdx.x, tid = threadIdx.x;
    int b = r >> 7, seg = r & 127;
    __shared__ int ids[8];
    if (tid < 8) ids[tid] = word_ids[b * Ss + seg * Ll + tid];
    __syncthreads();

    const unsigned* Ub = (const unsigned*)g_U;   // vocab-major: row = word id, 384 u32
    unsigned* d = (unsigned*)(g_decinb + (size_t)r * DIN + 768);

    int which = tid >> 6, p = tid & 63;
    float mx = -1e30f, my = -1e30f;

    if (which == 0) {
#pragma unroll
        for (int t = 0; t < 8; t++) {
            unsigned u = Ub[(size_t)ids[t] * 384 + p];
            mx = fmaxf(mx, bflo(u)); my = fmaxf(my, bfhi(u));
        }
        mx += b1[p * 2]; my += b1[p * 2 + 1];
    } else if (which == 1) {
#pragma unroll
        for (int t = 0; t < 7; t++) {
            unsigned u0 = Ub[(size_t)ids[t] * 384 + 64 + p];
            unsigned u1 = Ub[(size_t)ids[t + 1] * 384 + 128 + p];
            mx = fmaxf(mx, bflo(u0) + bflo(u1));
            my = fmaxf(my, bfhi(u0) + bfhi(u1));
        }
        mx += b2[p * 2]; my += b2[p * 2 + 1];
    } else {
#pragma unroll
        for (int t = 0; t < 6; t++) {
            unsigned u0 = Ub[(size_t)ids[t] * 384 + 192 + p];
            unsigned u1 = Ub[(size_t)ids[t + 1] * 384 + 256 + p];
            unsigned u2 = Ub[(size_t)ids[t + 2] * 384 + 320 + p];
            mx = fmaxf(mx, bflo(u0) + bflo(u1) + bflo(u2));
            my = fmaxf(my, bfhi(u0) + bfhi(u1) + bfhi(u2));
        }
        mx += b3[p * 2]; my += b3[p * 2 + 1];
    }
    d[which * 64 + p] = packbf(fmaxf(mx, 0.f), fmaxf(my, 0.f));
}

// ================= bf16 scan (R6/R9/R11-proven scan6) =================
#define SCP 520
#define SCAN_SMEM (32 * SCP * 2 + 8 * 32 * 34 * 4)   // 68096 B

__global__ __launch_bounds__(512, 1) void scan6(const float* __restrict__ Whh)
{
    extern __shared__ unsigned ssm[];
    __nv_bfloat16* hA = (__nv_bfloat16*)ssm;                 // [32][520]
    float* pbuf = (float*)((char*)ssm + 32 * SCP * 2);       // [8][32][34]

    int tid = threadIdx.x;
    int lane = tid & 31, w = tid >> 5;
    int grp = lane >> 2, tig = lane & 3;
    int mt = w & 1, kq = w >> 1;
    int cid = blockIdx.x;
    int bg = cid & 1;
    int j0 = (cid >> 1) * 8;

    unsigned bw[4][4][2];
#pragma unroll
    for (int nt = 0; nt < 4; nt++) {
        const float* wr = Whh + (size_t)(nt * H2 + j0 + grp) * H2 + kq * 64;
#pragma unroll
        for (int kc = 0; kc < 4; kc++) {
            const float* p = wr + kc * 16 + tig * 2;
            bw[nt][kc][0] = packbf(p[0], p[1]);
            bw[nt][kc][1] = packbf(p[8], p[9]);
        }
    }

    const __nv_bfloat16* ghb = g_hb;
    unsigned* pcount = &g_bar2[bg];

    float c_st = 0.f;
    int b_hat = tid >> 3, jj = tid & 7;     // epilogue item (tid<256)
    int row_global = bg * 32 + b_hat;
    size_t gx_base = (size_t)(row_global * NSEG) * G4 + (size_t)(j0 + jj);

    unsigned hA_u32 = (unsigned)__cvta_generic_to_shared(hA);
    unsigned dstbase = hA_u32 + (unsigned)((mt * 16) * (SCP * 2) + kq * 128);
    unsigned ldbase = hA_u32 + (unsigned)((mt * 16 + (lane & 15)) * (SCP * 2)
                                          + kq * 128 + ((lane >> 4) << 4));

    float gxi = 0.f, gxf = 0.f, gxg = 0.f, gxq = 0.f;
    if (tid < 256) {
        gxi = __ldg(&g_gx[gx_base]);
        gxf = __ldg(&g_gx[gx_base + 512]);
        gxg = __ldg(&g_gx[gx_base + 1024]);
        gxq = __ldg(&g_gx[gx_base + 1536]);
    }

    for (int t = 0; t < NSEG; t++) {
        {
            const __nv_bfloat16* src = ghb + (size_t)t * Bb * H2
                                     + (size_t)(bg * 32 + mt * 16) * H2 + kq * 64;
#pragma unroll
            for (int i = 0; i < 4; i++) {
                int c = lane + 32 * i;
                int r = c >> 3, ch = c & 7;
                CP_ASYNC16(dstbase + (unsigned)(r * (SCP * 2) + ch * 16),
                           src + r * H2 + ch * 8);
            }
            asm volatile("cp.async.commit_group;\n");
        }
        asm volatile("cp.async.wait_group 0;\n" ::: "memory");
        __syncwarp();

        float acc[4][4];
#pragma unroll
        for (int nt = 0; nt < 4; nt++)
#pragma unroll
            for (int i = 0; i < 4; i++) acc[nt][i] = 0.f;
#pragma unroll
        for (int kc = 0; kc < 4; kc++) {
            unsigned a0, a1, a2, a3;
            LDSM_X4(a0, a1, a2, a3, ldbase + kc * 32);
#pragma unroll
            for (int nt = 0; nt < 4; nt++)
                MMA_BF16(acc[nt], a0, a1, a2, a3, bw[nt][kc][0], bw[nt][kc][1]);
        }
        {
            float* pb = pbuf + kq * (32 * 34);
            int row = mt * 16 + grp;
#pragma unroll
            for (int nt = 0; nt < 4; nt++) {
                int c0 = nt * 8 + tig * 2;
                pb[row * 34 + c0]           = acc[nt][0];
                pb[row * 34 + c0 + 1]       = acc[nt][1];
                pb[(row + 8) * 34 + c0]     = acc[nt][2];
                pb[(row + 8) * 34 + c0 + 1] = acc[nt][3];
            }
        }
        __syncthreads();

        if (tid < 256) {
            float gsum[4];
#pragma unroll
            for (int q = 0; q < 4; q++) {
                int col = q * 8 + jj;
                float s = 0.f;
#pragma unroll
                for (int k = 0; k < 8; k++) s += pbuf[k * (32 * 34) + b_hat * 34 + col];
                gsum[q] = s;
            }
            float gi = gsum[0] + gxi;
            float gf = gsum[1] + gxf;
            float gg = gsum[2] + gxg;
            float go = gsum[3] + gxq;
            c_st = sigmf(gf) * c_st + sigmf(gi) * tanhfast(gg);
            float h = sigmf(go) * tanhfast(c_st);
            size_t ho = (size_t)(t + 1) * Bb * H2 + (size_t)row_global * H2 + j0 + jj;
            g_hb[ho] = __float2bfloat16(h);

            if (t + 1 < NSEG) {
                size_t gxo = gx_base + (size_t)(t + 1) * G4;
                gxi = __ldg(&g_gx[gxo]);
                gxf = __ldg(&g_gx[gxo + 512]);
                gxg = __ldg(&g_gx[gxo + 1024]);
                gxq = __ldg(&g_gx[gxo + 1536]);
            }
        }

        __syncthreads();
        if (t + 1 < NSEG) {
            if (tid == 0) {
                unsigned one = 1;
                asm volatile("red.release.gpu.global.add.u32 [%0], %1;"
                             :: "l"(pcount), "r"(one) : "memory");
                unsigned target = 64u * (unsigned)(t + 1);
                unsigned cur;
                do {
                    asm volatile("ld.acquire.gpu.global.u32 %0, [%1];"
                                 : "=r"(cur) : "l"(pcount));
                } while (cur < target);
            }
            __syncthreads();
        }
    }
}

// ---------------- launcher ----------------
extern "C" void kernel_launch(void* const* d_in, const int* in_sizes, int n_in,
                              void* d_out, int out_size)
{
    const int*   word_ids = (const int*)d_in[0];
    const float* embed    = (const float*)d_in[1];
    const float* enc      = (const float*)d_in[2];
    const float* w1       = (const float*)d_in[3];
    const float* b1       = (const float*)d_in[4];
    const float* w2       = (const float*)d_in[5];
    const float* b2       = (const float*)d_in[6];
    const float* w3       = (const float*)d_in[7];
    const float* b3       = (const float*)d_in[8];
    const float* Wih      = (const float*)d_in[9];
    const float* Whh      = (const float*)d_in[10];
    const float* Wfc      = (const float*)d_in[11];
    float* out = (float*)d_out;

    void *pU, *pWallb, *pEmbb, *pDecinb, *pWihb, *pWfcb, *pGx, *pHb;
    cudaGetSymbolAddress(&pU, g_U);
    cudaGetSymbolAddress(&pWallb, g_Wallb);
    cudaGetSymbolAddress(&pEmbb, g_embb);
    cudaGetSymbolAddress(&pDecinb, g_decinb);
    cudaGetSymbolAddress(&pWihb, g_Wihb);
    cudaGetSymbolAddress(&pWfcb, g_Wfcb);
    cudaGetSymbolAddress(&pGx, g_gx);
    cudaGetSymbolAddress(&pHb, g_hb);

    cudaFuncSetAttribute(gemmb, cudaFuncAttributeMaxDynamicSharedMemorySize, GEMMB_SMEM);
    cudaFuncSetAttribute(gemmU, cudaFuncAttributeMaxDynamicSharedMemorySize, GEMMB_SMEM);
    cudaFuncSetAttribute(gemm_lsm, cudaFuncAttributeMaxDynamicSharedMemorySize, LSM_SMEM);
    cudaFuncSetAttribute(scan6, cudaFuncAttributeMaxDynamicSharedMemorySize, SCAN_SMEM);

    prep<<<PREP_BLOCKS, 256>>>(word_ids, embed, Wih, w1, w2, w3, Wfc, enc);

    // conv taps PER VOCAB WORD: U_bf16[50000(p128),768] = embed_bf16 @ Wall_bf16^T
    gemmU<<<dim3(768 / BBN, (Vv + BBM - 1) / BBM), 256, GEMMB_SMEM>>>(
        (const __nv_bfloat16*)pEmbb, (const __nv_bfloat16*)pWallb,
        (__nv_bfloat16*)pU, Vv, 768, Dd);
    conv_reduce<<<NSEGT, 192>>>(word_ids, b1, b2, b3);

    // gates_x[8192,2048] = dec_in_bf16 @ W_ih_bf16^T
    gemmb<<<dim3(G4 / BBN, NSEGT / BBM), 256, GEMMB_SMEM>>>(
        (const __nv_bfloat16*)pDecinb, (const __nv_bfloat16*)pWihb,
        (float*)pGx, NSEGT, G4, DIN);

    scan6<<<128, 512, SCAN_SMEM>>>(Whh);

    // fused logits + log_softmax (bf16 h, bf16 W_fc)
    gemm_lsm<<<NSEGT / LBM, 256, LSM_SMEM>>>(
        (const __nv_bfloat16*)pHb + (size_t)Bb * H2,
        (const __nv_bfloat16*)pWfcb, out);
}

// round 17
// speedup vs baseline: 1.1516x; 1.0005x over previous
#include <cuda_runtime.h>
#include <cuda_bf16.h>
#include <math.h>

// ---------------- problem constants ----------------
#define Bb    64
#define Ss    1024
#define Dd    256
#define Hh    256
#define H2    512
#define Ff    128
#define Tt    64
#define Ll    8
#define NSEG  128
#define DIN   1152
#define G4    2048           // 4 * H2
#define NROWS 65536          // B * S
#define NSEGT 8192           // B * NSEG
#define Vv    50000

// ---------------- scratch (static device, no allocs) ----------------
__device__ __nv_bfloat16 g_decinb[NSEGT * DIN];          // bf16 dec_in
__device__ __nv_bfloat16 g_U[(size_t)NROWS * 768];       // bf16 conv taps (per-vocab; slack)
__device__ __nv_bfloat16 g_Wallb[768 * Dd];              // bf16 stacked conv W
__device__ __nv_bfloat16 g_embb[(size_t)Vv * Dd];        // bf16 embed table
__device__ __nv_bfloat16 g_Wihb[(size_t)G4 * DIN];       // bf16 W_ih
__device__ __nv_bfloat16 g_Wfcb[Tt * H2];                // bf16 W_fc
__device__ float g_gx[(size_t)NSEGT * G4];
__device__ __nv_bfloat16 g_hb[(size_t)129 * Bb * H2];    // bf16 h
__device__ unsigned g_bar2[2];

// ---------------- helpers ----------------
__device__ __forceinline__ float sigmf(float x) { return 1.f / (1.f + __expf(-x)); }
__device__ __forceinline__ float tanhfast(float x) { return 2.f / (1.f + __expf(-2.f * x)) - 1.f; }
__device__ __forceinline__ unsigned packbf(float lo, float hi) {
    unsigned d;
    asm("cvt.rn.bf16x2.f32 %0, %1, %2;" : "=r"(d) : "f"(hi), "f"(lo));
    return d;
}
__device__ __forceinline__ float bflo(unsigned u) { return __uint_as_float(u << 16); }
__device__ __forceinline__ float bfhi(unsigned u) { return __uint_as_float(u & 0xffff0000u); }

#define MMA_BF16(acc, a0, a1, a2, a3, b0, b1)                                  \
    asm("mma.sync.aligned.m16n8k16.row.col.f32.bf16.bf16.f32 "                 \
        "{%0,%1,%2,%3},{%4,%5,%6,%7},{%8,%9},{%0,%1,%2,%3};"                   \
        : "+f"(acc[0]), "+f"(acc[1]), "+f"(acc[2]), "+f"(acc[3])               \
        : "r"(a0), "r"(a1), "r"(a2), "r"(a3), "r"(b0), "r"(b1))

#define LDSM_X4(r0, r1, r2, r3, addr)                                          \
    asm volatile("ldmatrix.sync.aligned.m8n8.x4.shared.b16 {%0,%1,%2,%3}, [%4];" \
                 : "=r"(r0), "=r"(r1), "=r"(r2), "=r"(r3) : "r"(addr))

#define CP_ASYNC16(dst, src)                                                   \
    asm volatile("cp.async.cg.shared.global [%0], [%1], 16;\n" ::              \
                 "r"(dst), "l"(src))

// ======== 128x128 bf16 GEMM (gates), 3-stage pipeline: C fp32 = A @ B^T =====
#define BBM 128
#define BBN 128
#define BBK 64
#define GEMMB_SMEM (3 * (BBM + BBN) * 144)   // 110592 B

__global__ __launch_bounds__(256, 2) void gemmb(
    const __nv_bfloat16* __restrict__ A, const __nv_bfloat16* __restrict__ Bw,
    float* __restrict__ C, int M, int N, int K)
{
    extern __shared__ unsigned short bsm[];

    int tid = threadIdx.x;
    int mBase = blockIdx.y * BBM, nBase = blockIdx.x * BBN;

    int w = tid >> 5, lane = tid & 31;
    int grp = lane >> 2, tig = lane & 3;
    int wm = w & 1, wn = w >> 1;       // 2x4 warp grid, warp tile 64x32

    unsigned smbase = (unsigned)__cvta_generic_to_shared(bsm);
    unsigned bbase = smbase + 3 * BBM * 144;

    unsigned aAddr0 = smbase + (unsigned)((wm * 64 + (lane & 15)) * 144 + ((lane >> 4) << 4));
    unsigned bAddr0 = bbase + (unsigned)((wn * 32 + (lane & 15)) * 144 + ((lane >> 4) << 4));

    float acc[4][4][4];
#pragma unroll
    for (int mt = 0; mt < 4; mt++)
#pragma unroll
        for (int nt = 0; nt < 4; nt++)
#pragma unroll
            for (int i = 0; i < 4; i++) acc[mt][nt][i] = 0.f;

    int nkt = K / BBK;

#define BLOAD(s, kt) do {                                                       \
        int koff = (kt) * BBK;                                                  \
        _Pragma("unroll")                                                       \
        for (int i = 0; i < 4; i++) {                                           \
            int cid = tid + i * 256;                                            \
            int row = cid >> 3, ch = cid & 7;                                   \
            const __nv_bfloat16* src = A + (size_t)(mBase + row) * K + koff + ch * 8; \
            unsigned dst = smbase + (unsigned)(((s) * BBM + row) * 144 + ch * 16);    \
            CP_ASYNC16(dst, src);                                               \
        }                                                                       \
        _Pragma("unroll")                                                       \
        for (int i = 0; i < 4; i++) {                                           \
            int cid = tid + i * 256;                                            \
            int row = cid >> 3, ch = cid & 7;                                   \
            const __nv_bfloat16* src = Bw + (size_t)(nBase + row) * K + koff + ch * 8; \
            unsigned dst = bbase + (unsigned)(((s) * BBN + row) * 144 + ch * 16);     \
            CP_ASYNC16(dst, src);                                               \
        }                                                                       \
        asm volatile("cp.async.commit_group;\n");                               \
    } while (0)

    BLOAD(0, 0);
    BLOAD(1, 1);

    int s = 0;
    for (int kt = 0; kt < nkt; kt++) {
        if (kt + 2 < nkt) {
            int s2 = s + 2; if (s2 >= 3) s2 -= 3;
            BLOAD(s2, kt + 2);
            asm volatile("cp.async.wait_group 2;\n" ::: "memory");
        } else if (kt + 1 < nkt) {
            asm volatile("cp.async.wait_group 1;\n" ::: "memory");
        } else {
            asm volatile("cp.async.wait_group 0;\n" ::: "memory");
        }
        __syncthreads();

        unsigned aS = aAddr0 + (unsigned)(s * BBM * 144);
        unsigned bS = bAddr0 + (unsigned)(s * BBN * 144);
#pragma unroll
        for (int kc = 0; kc < 4; kc++) {
            unsigned kb = kc * 32;
            unsigned bfr[2][4];
#pragma unroll
            for (int ntp = 0; ntp < 2; ntp++)
                LDSM_X4(bfr[ntp][0], bfr[ntp][1], bfr[ntp][2], bfr[ntp][3],
                        bS + ntp * (16 * 144) + kb);
#pragma unroll
            for (int mt = 0; mt < 4; mt++) {
                unsigned a0, a1, a2, a3;
                LDSM_X4(a0, a1, a2, a3, aS + mt * (16 * 144) + kb);
                MMA_BF16(acc[mt][0], a0, a1, a2, a3, bfr[0][0], bfr[0][2]);
                MMA_BF16(acc[mt][1], a0, a1, a2, a3, bfr[0][1], bfr[0][3]);
                MMA_BF16(acc[mt][2], a0, a1, a2, a3, bfr[1][0], bfr[1][2]);
                MMA_BF16(acc[mt][3], a0, a1, a2, a3, bfr[1][1], bfr[1][3]);
            }
        }
        __syncthreads();
        if (++s == 3) s = 0;
    }

#pragma unroll
    for (int mt = 0; mt < 4; mt++) {
        int row0 = mBase + wm * 64 + mt * 16 + grp;
#pragma unroll
        for (int nt = 0; nt < 4; nt++) {
            int col = nBase + wn * 32 + nt * 8 + tig * 2;
            *(float2*)&C[(size_t)row0 * N + col] = make_float2(acc[mt][nt][0], acc[mt][nt][1]);
            *(float2*)&C[(size_t)(row0 + 8) * N + col] = make_float2(acc[mt][nt][2], acc[mt][nt][3]);
        }
    }
}

// == 128x128 bf16 GEMM over VOCAB, 3-stage, bf16 out (conv taps, clamped) ====
__global__ __launch_bounds__(256, 2) void gemmU(
    const __nv_bfloat16* __restrict__ A, const __nv_bfloat16* __restrict__ Bw,
    __nv_bfloat16* __restrict__ C, int M, int N, int K)
{
    extern __shared__ unsigned short bsm[];

    int tid = threadIdx.x;
    int mBase = blockIdx.y * BBM, nBase = blockIdx.x * BBN;

    int w = tid >> 5, lane = tid & 31;
    int grp = lane >> 2, tig = lane & 3;
    int wm = w & 1, wn = w >> 1;

    unsigned smbase = (unsigned)__cvta_generic_to_shared(bsm);
    unsigned bbase = smbase + 3 * BBM * 144;

    unsigned aAddr0 = smbase + (unsigned)((wm * 64 + (lane & 15)) * 144 + ((lane >> 4) << 4));
    unsigned bAddr0 = bbase + (unsigned)((wn * 32 + (lane & 15)) * 144 + ((lane >> 4) << 4));

    float acc[4][4][4];
#pragma unroll
    for (int mt = 0; mt < 4; mt++)
#pragma unroll
        for (int nt = 0; nt < 4; nt++)
#pragma unroll
            for (int i = 0; i < 4; i++) acc[mt][nt][i] = 0.f;

    int nkt = K / BBK;   // 4

#define ULOAD(s, kt) do {                                                       \
        int koff = (kt) * BBK;                                                  \
        _Pragma("unroll")                                                       \
        for (int i = 0; i < 4; i++) {                                           \
            int cid = tid + i * 256;                                            \
            int row = cid >> 3, ch = cid & 7;                                   \
            int ar = mBase + row; if (ar >= M) ar = M - 1;                      \
            const __nv_bfloat16* src = A + (size_t)ar * K + koff + ch * 8;      \
            unsigned dst = smbase + (unsigned)(((s) * BBM + row) * 144 + ch * 16);    \
            CP_ASYNC16(dst, src);                                               \
        }                                                                       \
        _Pragma("unroll")                                                       \
        for (int i = 0; i < 4; i++) {                                           \
            int cid = tid + i * 256;                                            \
            int row = cid >> 3, ch = cid & 7;                                   \
            const __nv_bfloat16* src = Bw + (size_t)(nBase + row) * K + koff + ch * 8; \
            unsigned dst = bbase + (unsigned)(((s) * BBN + row) * 144 + ch * 16);     \
            CP_ASYNC16(dst, src);                                               \
        }                                                                       \
        asm volatile("cp.async.commit_group;\n");                               \
    } while (0)

    ULOAD(0, 0);
    ULOAD(1, 1);

    int s = 0;
    for (int kt = 0; kt < nkt; kt++) {
        if (kt + 2 < nkt) {
            int s2 = s + 2; if (s2 >= 3) s2 -= 3;
            ULOAD(s2, kt + 2);
            asm volatile("cp.async.wait_group 2;\n" ::: "memory");
        } else if (kt + 1 < nkt) {
            asm volatile("cp.async.wait_group 1;\n" ::: "memory");
        } else {
            asm volatile("cp.async.wait_group 0;\n" ::: "memory");
        }
        __syncthreads();

        unsigned aS = aAddr0 + (unsigned)(s * BBM * 144);
        unsigned bS = bAddr0 + (unsigned)(s * BBN * 144);
#pragma unroll
        for (int kc = 0; kc < 4; kc++) {
            unsigned kb = kc * 32;
            unsigned bfr[2][4];
#pragma unroll
            for (int ntp = 0; ntp < 2; ntp++)
                LDSM_X4(bfr[ntp][0], bfr[ntp][1], bfr[ntp][2], bfr[ntp][3],
                        bS + ntp * (16 * 144) + kb);
#pragma unroll
            for (int mt = 0; mt < 4; mt++) {
                unsigned a0, a1, a2, a3;
                LDSM_X4(a0, a1, a2, a3, aS + mt * (16 * 144) + kb);
                MMA_BF16(acc[mt][0], a0, a1, a2, a3, bfr[0][0], bfr[0][2]);
                MMA_BF16(acc[mt][1], a0, a1, a2, a3, bfr[0][1], bfr[0][3]);
                MMA_BF16(acc[mt][2], a0, a1, a2, a3, bfr[1][0], bfr[1][2]);
                MMA_BF16(acc[mt][3], a0, a1, a2, a3, bfr[1][1], bfr[1][3]);
            }
        }
        __syncthreads();
        if (++s == 3) s = 0;
    }

#pragma unroll
    for (int mt = 0; mt < 4; mt++) {
        int row0 = mBase + wm * 64 + mt * 16 + grp;
#pragma unroll
        for (int nt = 0; nt < 4; nt++) {
            int col = nBase + wn * 32 + nt * 8 + tig * 2;
            *(unsigned*)&C[(size_t)row0 * N + col] = packbf(acc[mt][nt][0], acc[mt][nt][1]);
            *(unsigned*)&C[(size_t)(row0 + 8) * N + col] = packbf(acc[mt][nt][2], acc[mt][nt][3]);
        }
    }
}

// ======== fused logits GEMM (bf16) + log_softmax + output permutation ========
#define LBM 128
#define LBN 64
#define LSM_SMEM (2 * (LBM + LBN) * 144)   // 55296 B

__global__ __launch_bounds__(256, 2) void gemm_lsm(
    const __nv_bfloat16* __restrict__ A, const __nv_bfloat16* __restrict__ Bw,
    float* __restrict__ out)
{
    extern __shared__ unsigned short bsm[];
    float* ls = (float*)bsm;

    int tid = threadIdx.x;
    int mBase = blockIdx.x * LBM;

    int w = tid >> 5, lane = tid & 31;
    int grp = lane >> 2, tig = lane & 3;
    int wm = w & 3, wn = w >> 2;

    unsigned smbase = (unsigned)__cvta_generic_to_shared(bsm);
    unsigned bbase = smbase + 2 * LBM * 144;

    unsigned aAddr0 = smbase + (unsigned)((wm * 32 + (lane & 15)) * 144 + ((lane >> 4) << 4));
    unsigned bAddr0 = bbase + (unsigned)((wn * 32 + (lane & 15)) * 144 + ((lane >> 4) << 4));

    float acc[2][4][4];
#pragma unroll
    for (int mt = 0; mt < 2; mt++)
#pragma unroll
        for (int nt = 0; nt < 4; nt++)
#pragma unroll
            for (int i = 0; i < 4; i++) acc[mt][nt][i] = 0.f;

#define LLOAD(s, kt) do {                                                       \
        int koff = (kt) * BBK;                                                  \
        _Pragma("unroll")                                                       \
        for (int i = 0; i < 4; i++) {                                           \
            int cid = tid + i * 256;                                            \
            int row = cid >> 3, ch = cid & 7;                                   \
            const __nv_bfloat16* src = A + (size_t)(mBase + row) * H2 + koff + ch * 8; \
            unsigned dst = smbase + (unsigned)(((s) * LBM + row) * 144 + ch * 16);     \
            CP_ASYNC16(dst, src);                                               \
        }                                                                       \
        _Pragma("unroll")                                                       \
        for (int i = 0; i < 2; i++) {                                           \
            int cid = tid + i * 256;                                            \
            int row = cid >> 3, ch = cid & 7;                                   \
            const __nv_bfloat16* src = Bw + (size_t)row * H2 + koff + ch * 8;   \
            unsigned dst = bbase + (unsigned)(((s) * LBN + row) * 144 + ch * 16);     \
            CP_ASYNC16(dst, src);                                               \
        }                                                                       \
        asm volatile("cp.async.commit_group;\n");                               \
    } while (0)

    LLOAD(0, 0);

    const int nkt = H2 / BBK;   // 8
    for (int kt = 0; kt < nkt; kt++) {
        int s = kt & 1;
        if (kt + 1 < nkt) {
            LLOAD((kt + 1) & 1, kt + 1);
            asm volatile("cp.async.wait_group 1;\n" ::: "memory");
        } else {
            asm volatile("cp.async.wait_group 0;\n" ::: "memory");
        }
        __syncthreads();

        unsigned aS = aAddr0 + (unsigned)(s * LBM * 144);
        unsigned bS = bAddr0 + (unsigned)(s * LBN * 144);
#pragma unroll
        for (int kc = 0; kc < 4; kc++) {
            unsigned kb = kc * 32;
            unsigned bfr[2][4];
#pragma unroll
            for (int ntp = 0; ntp < 2; ntp++)
                LDSM_X4(bfr[ntp][0], bfr[ntp][1], bfr[ntp][2], bfr[ntp][3],
                        bS + ntp * (16 * 144) + kb);
#pragma unroll
            for (int mt = 0; mt < 2; mt++) {
                unsigned a0, a1, a2, a3;
                LDSM_X4(a0, a1, a2, a3, aS + mt * (16 * 144) + kb);
                MMA_BF16(acc[mt][0], a0, a1, a2, a3, bfr[0][0], bfr[0][2]);
                MMA_BF16(acc[mt][1], a0, a1, a2, a3, bfr[0][1], bfr[0][3]);
                MMA_BF16(acc[mt][2], a0, a1, a2, a3, bfr[1][0], bfr[1][2]);
                MMA_BF16(acc[mt][3], a0, a1, a2, a3, bfr[1][1], bfr[1][3]);
            }
        }
        __syncthreads();
    }

#pragma unroll
    for (int mt = 0; mt < 2; mt++) {
        int row0 = wm * 32 + mt * 16 + grp;
#pragma unroll
        for (int nt = 0; nt < 4; nt++) {
            int col = wn * 32 + nt * 8 + tig * 2;
            *(float2*)&ls[row0 * 68 + col] = make_float2(acc[mt][nt][0], acc[mt][nt][1]);
            *(float2*)&ls[(row0 + 8) * 68 + col] = make_float2(acc[mt][nt][2], acc[mt][nt][3]);
        }
    }
    __syncthreads();

#pragma unroll 4
    for (int rr = 0; rr < 16; rr++) {
        int row = w * 16 + rr;
        float2 v = *(const float2*)&ls[row * 68 + lane * 2];
        float m = fmaxf(v.x, v.y);
#pragma unroll
        for (int o = 16; o; o >>= 1) m = fmaxf(m, __shfl_xor_sync(0xffffffffu, m, o));
        float s = expf(v.x - m) + expf(v.y - m);
#pragma unroll
        for (int o = 16; o; o >>= 1) s += __shfl_xor_sync(0xffffffffu, s, o);
        float lse = m + logf(s);
        int r = mBase + row;
        int t = r >> 6, bb = r & 63;
        *(float2*)&out[(size_t)(bb * NSEG + t) * Tt + lane * 2] =
            make_float2(v.x - lse, v.y - lse);
    }
}

// ------- fused prep: seg_feat | cvt_emb | cvt_wih | pack_wall | cvt_wfc | h0 -
#define PREP_S NSEGT
#define PREP_E 12500
#define PREP_W 2304
#define PREP_P 384
#define PREP_F 32
#define PREP_H 64
#define PREP_BLOCKS (PREP_S + PREP_E + PREP_W + PREP_P + PREP_F + PREP_H)

__global__ __launch_bounds__(256) void prep(
    const int* __restrict__ word_ids,
    const float* __restrict__ embed, const float* __restrict__ Wih,
    const float* __restrict__ w1, const float* __restrict__ w2,
    const float* __restrict__ w3, const float* __restrict__ Wfc,
    const float* __restrict__ enc)
{
    int bid = blockIdx.x, tid = threadIdx.x;
    if (bid < PREP_S) {
        int r = bid;
        int b = r >> 7, seg = r & 127;
        __shared__ int ids[8];
        if (tid < 8) ids[tid] = word_ids[b * Ss + seg * Ll + tid];
        __syncthreads();
        {
            float s = 0.f;
#pragma unroll
            for (int t = 0; t < 8; t++) s += embed[(size_t)ids[t] * Dd + tid];
            g_decinb[(size_t)r * DIN + tid] = __float2bfloat16(s * 0.125f);
        }
        for (int k = tid; k < H2; k += 256) {
            float s = 0.f;
#pragma unroll
            for (int t = 0; t < 8; t++) s += enc[(size_t)(b * Ss + seg * Ll + t) * H2 + k];
            g_decinb[(size_t)r * DIN + Dd + k] = __float2bfloat16(s * 0.125f);
        }
        return;
    }
    bid -= PREP_S;
    if (bid < PREP_E) {
        size_t i = ((size_t)bid * 256 + tid) * 4;
        float4 v = *(const float4*)(embed + i);
        *(uint2*)((unsigned short*)g_embb + i) =
            make_uint2(packbf(v.x, v.y), packbf(v.z, v.w));
        return;
    }
    bid -= PREP_E;
    if (bid < PREP_W) {
        size_t i = ((size_t)bid * 256 + tid) * 4;
        float4 v = *(const float4*)(Wih + i);
        *(uint2*)((unsigned short*)g_Wihb + i) =
            make_uint2(packbf(v.x, v.y), packbf(v.z, v.w));
        return;
    }
    bid -= PREP_W;
    if (bid < PREP_P) {
        int n = bid * 2 + (tid >> 7);
        int k = tid & 127;
        const float* src;
        if (n < 128)       src = w1 + n * Dd;
        else if (n < 384) { int m = n - 128; src = w2 + ((m & 127) * 2 + (m >> 7)) * Dd; }
        else              { int m = n - 384; src = w3 + ((m & 127) * 3 + (m >> 7)) * Dd; }
        *(unsigned*)&g_Wallb[n * Dd + k * 2] = packbf(src[k * 2], src[k * 2 + 1]);
        return;
    }
    bid -= PREP_P;
    if (bid < PREP_F) {
        size_t i = ((size_t)bid * 256 + tid) * 4;
        float4 v = *(const float4*)(Wfc + i);
        *(uint2*)((unsigned short*)g_Wfcb + i) =
            make_uint2(packbf(v.x, v.y), packbf(v.z, v.w));
        return;
    }
    bid -= PREP_F;
    {
        if (bid == 0 && tid < 2) g_bar2[tid] = 0;
        int b = bid;
        for (int j = tid; j < H2; j += 256) {
            float v = (j < Hh) ? enc[(size_t)(b * Ss + Ss - 1) * H2 + j]
                               : enc[(size_t)(b * Ss) * H2 + j];
            g_hb[(size_t)b * H2 + j] = __float2bfloat16(v);
        }
    }
}

// -------- conv tap-sum + relu + maxpool (vocab-gathered, bf16x2) --------
__global__ __launch_bounds__(192) void conv_reduce(
    const int* __restrict__ word_ids,
    const float* __restrict__ b1, const float* __restrict__ b2, const float* __restrict__ b3)
{
    int r = blockIdx.x, tid = threadIdx.x;
    int b = r >> 7, seg = r & 127;
    __shared__ int ids[8];
    if (tid < 8) ids[tid] = word_ids[b * Ss + seg * Ll + tid];
    __syncthreads();

    const unsigned* Ub = (const unsigned*)g_U;   // vocab-major: row = word id, 384 u32
    unsigned* d = (unsigned*)(g_decinb + (size_t)r * DIN + 768);

    int which = tid >> 6, p = tid & 63;
    float mx = -1e30f, my = -1e30f;

    if (which == 0) {
#pragma unroll
        for (int t = 0; t < 8; t++) {
            unsigned u = Ub[(size_t)ids[t] * 384 + p];
            mx = fmaxf(mx, bflo(u)); my = fmaxf(my, bfhi(u));
        }
        mx += b1[p * 2]; my += b1[p * 2 + 1];
    } else if (which == 1) {
#pragma unroll
        for (int t = 0; t < 7; t++) {
            unsigned u0 = Ub[(size_t)ids[t] * 384 + 64 + p];
            unsigned u1 = Ub[(size_t)ids[t + 1] * 384 + 128 + p];
            mx = fmaxf(mx, bflo(u0) + bflo(u1));
            my = fmaxf(my, bfhi(u0) + bfhi(u1));
        }
        mx += b2[p * 2]; my += b2[p * 2 + 1];
    } else {
#pragma unroll
        for (int t = 0; t < 6; t++) {
            unsigned u0 = Ub[(size_t)ids[t] * 384 + 192 + p];
            unsigned u1 = Ub[(size_t)ids[t + 1] * 384 + 256 + p];
            unsigned u2 = Ub[(size_t)ids[t + 2] * 384 + 320 + p];
            mx = fmaxf(mx, bflo(u0) + bflo(u1) + bflo(u2));
            my = fmaxf(my, bfhi(u0) + bfhi(u1) + bfhi(u2));
        }
        mx += b3[p * 2]; my += b3[p * 2 + 1];
    }
    d[which * 64 + p] = packbf(fmaxf(mx, 0.f), fmaxf(my, 0.f));
}

// ================= bf16 scan (R6/R9/R11-proven scan6) =================
#define SCP 520
#define SCAN_SMEM (32 * SCP * 2 + 8 * 32 * 34 * 4)   // 68096 B

__global__ __launch_bounds__(512, 1) void scan6(const float* __restrict__ Whh)
{
    extern __shared__ unsigned ssm[];
    __nv_bfloat16* hA = (__nv_bfloat16*)ssm;                 // [32][520]
    float* pbuf = (float*)((char*)ssm + 32 * SCP * 2);       // [8][32][34]

    int tid = threadIdx.x;
    int lane = tid & 31, w = tid >> 5;
    int grp = lane >> 2, tig = lane & 3;
    int mt = w & 1, kq = w >> 1;
    int cid = blockIdx.x;
    int bg = cid & 1;
    int j0 = (cid >> 1) * 8;

    unsigned bw[4][4][2];
#pragma unroll
    for (int nt = 0; nt < 4; nt++) {
        const float* wr = Whh + (size_t)(nt * H2 + j0 + grp) * H2 + kq * 64;
#pragma unroll
        for (int kc = 0; kc < 4; kc++) {
            const float* p = wr + kc * 16 + tig * 2;
            bw[nt][kc][0] = packbf(p[0], p[1]);
            bw[nt][kc][1] = packbf(p[8], p[9]);
        }
    }

    const __nv_bfloat16* ghb = g_hb;
    unsigned* pcount = &g_bar2[bg];

    float c_st = 0.f;
    int b_hat = tid >> 3, jj = tid & 7;     // epilogue item (tid<256)
    int row_global = bg * 32 + b_hat;
    size_t gx_base = (size_t)(row_global * NSEG) * G4 + (size_t)(j0 + jj);

    unsigned hA_u32 = (unsigned)__cvta_generic_to_shared(hA);
    unsigned dstbase = hA_u32 + (unsigned)((mt * 16) * (SCP * 2) + kq * 128);
    unsigned ldbase = hA_u32 + (unsigned)((mt * 16 + (lane & 15)) * (SCP * 2)
                                          + kq * 128 + ((lane >> 4) << 4));

    float gxi = 0.f, gxf = 0.f, gxg = 0.f, gxq = 0.f;
    if (tid < 256) {
        gxi = __ldg(&g_gx[gx_base]);
        gxf = __ldg(&g_gx[gx_base + 512]);
        gxg = __ldg(&g_gx[gx_base + 1024]);
        gxq = __ldg(&g_gx[gx_base + 1536]);
    }

    for (int t = 0; t < NSEG; t++) {
        {
            const __nv_bfloat16* src = ghb + (size_t)t * Bb * H2
                                     + (size_t)(bg * 32 + mt * 16) * H2 + kq * 64;
#pragma unroll
            for (int i = 0; i < 4; i++) {
                int c = lane + 32 * i;
                int r = c >> 3, ch = c & 7;
                CP_ASYNC16(dstbase + (unsigned)(r * (SCP * 2) + ch * 16),
                           src + r * H2 + ch * 8);
            }
            asm volatile("cp.async.commit_group;\n");
        }
        asm volatile("cp.async.wait_group 0;\n" ::: "memory");
        __syncwarp();

        float acc[4][4];
#pragma unroll
        for (int nt = 0; nt < 4; nt++)
#pragma unroll
            for (int i = 0; i < 4; i++) acc[nt][i] = 0.f;
#pragma unroll
        for (int kc = 0; kc < 4; kc++) {
            unsigned a0, a1, a2, a3;
            LDSM_X4(a0, a1, a2, a3, ldbase + kc * 32);
#pragma unroll
            for (int nt = 0; nt < 4; nt++)
                MMA_BF16(acc[nt], a0, a1, a2, a3, bw[nt][kc][0], bw[nt][kc][1]);
        }
        {
            float* pb = pbuf + kq * (32 * 34);
            int row = mt * 16 + grp;
#pragma unroll
            for (int nt = 0; nt < 4; nt++) {
                int c0 = nt * 8 + tig * 2;
                pb[row * 34 + c0]           = acc[nt][0];
                pb[row * 34 + c0 + 1]       = acc[nt][1];
                pb[(row + 8) * 34 + c0]     = acc[nt][2];
                pb[(row + 8) * 34 + c0 + 1] = acc[nt][3];
            }
        }
        __syncthreads();

        if (tid < 256) {
            float gsum[4];
#pragma unroll
            for (int q = 0; q < 4; q++) {
                int col = q * 8 + jj;
                float s = 0.f;
#pragma unroll
                for (int k = 0; k < 8; k++) s += pbuf[k * (32 * 34) + b_hat * 34 + col];
                gsum[q] = s;
            }
            float gi = gsum[0] + gxi;
            float gf = gsum[1] + gxf;
            float gg = gsum[2] + gxg;
            float go = gsum[3] + gxq;
            c_st = sigmf(gf) * c_st + sigmf(gi) * tanhfast(gg);
            float h = sigmf(go) * tanhfast(c_st);
            size_t ho = (size_t)(t + 1) * Bb * H2 + (size_t)row_global * H2 + j0 + jj;
            g_hb[ho] = __float2bfloat16(h);

            if (t + 1 < NSEG) {
                size_t gxo = gx_base + (size_t)(t + 1) * G4;
                gxi = __ldg(&g_gx[gxo]);
                gxf = __ldg(&g_gx[gxo + 512]);
                gxg = __ldg(&g_gx[gxo + 1024]);
                gxq = __ldg(&g_gx[gxo + 1536]);
            }
        }

        __syncthreads();
        if (t + 1 < NSEG) {
            if (tid == 0) {
                unsigned one = 1;
                asm volatile("red.release.gpu.global.add.u32 [%0], %1;"
                             :: "l"(pcount), "r"(one) : "memory");
                unsigned target = 64u * (unsigned)(t + 1);
                unsigned cur;
                do {
                    asm volatile("ld.acquire.gpu.global.u32 %0, [%1];"
                                 : "=r"(cur) : "l"(pcount));
                } while (cur < target);
            }
            __syncthreads();
        }
    }
}

// ---------------- launcher ----------------
extern "C" void kernel_launch(void* const* d_in, const int* in_sizes, int n_in,
                              void* d_out, int out_size)
{
    const int*   word_ids = (const int*)d_in[0];
    const float* embed    = (const float*)d_in[1];
    const float* enc      = (const float*)d_in[2];
    const float* w1       = (const float*)d_in[3];
    const float* b1       = (const float*)d_in[4];
    const float* w2       = (const float*)d_in[5];
    const float* b2       = (const float*)d_in[6];
    const float* w3       = (const float*)d_in[7];
    const float* b3       = (const float*)d_in[8];
    const float* Wih      = (const float*)d_in[9];
    const float* Whh      = (const float*)d_in[10];
    const float* Wfc      = (const float*)d_in[11];
    float* out = (float*)d_out;

    void *pU, *pWallb, *pEmbb, *pDecinb, *pWihb, *pWfcb, *pGx, *pHb;
    cudaGetSymbolAddress(&pU, g_U);
    cudaGetSymbolAddress(&pWallb, g_Wallb);
    cudaGetSymbolAddress(&pEmbb, g_embb);
    cudaGetSymbolAddress(&pDecinb, g_decinb);
    cudaGetSymbolAddress(&pWihb, g_Wihb);
    cudaGetSymbolAddress(&pWfcb, g_Wfcb);
    cudaGetSymbolAddress(&pGx, g_gx);
    cudaGetSymbolAddress(&pHb, g_hb);

    cudaFuncSetAttribute(gemmb, cudaFuncAttributeMaxDynamicSharedMemorySize, GEMMB_SMEM);
    cudaFuncSetAttribute(gemmU, cudaFuncAttributeMaxDynamicSharedMemorySize, GEMMB_SMEM);
    cudaFuncSetAttribute(gemm_lsm, cudaFuncAttributeMaxDynamicSharedMemorySize, LSM_SMEM);
    cudaFuncSetAttribute(scan6, cudaFuncAttributeMaxDynamicSharedMemorySize, SCAN_SMEM);

    prep<<<PREP_BLOCKS, 256>>>(word_ids, embed, Wih, w1, w2, w3, Wfc, enc);

    // conv taps PER VOCAB WORD: U_bf16[50000(p128),768] = embed_bf16 @ Wall_bf16^T
    gemmU<<<dim3(768 / BBN, (Vv + BBM - 1) / BBM), 256, GEMMB_SMEM>>>(
        (const __nv_bfloat16*)pEmbb, (const __nv_bfloat16*)pWallb,
        (__nv_bfloat16*)pU, Vv, 768, Dd);
    conv_reduce<<<NSEGT, 192>>>(word_ids, b1, b2, b3);

    // gates_x[8192,2048] = dec_in_bf16 @ W_ih_bf16^T
    gemmb<<<dim3(G4 / BBN, NSEGT / BBM), 256, GEMMB_SMEM>>>(
        (const __nv_bfloat16*)pDecinb, (const __nv_bfloat16*)pWihb,
        (float*)pGx, NSEGT, G4, DIN);

    scan6<<<128, 512, SCAN_SMEM>>>(Whh);

    // fused logits + log_softmax (bf16 h, bf16 W_fc)
    gemm_lsm<<<NSEGT / LBM, 256, LSM_SMEM>>>(
        (const __nv_bfloat16*)pHb + (size_t)Bb * H2,
        (const __nv_bfloat16*)pWfcb, out);
}